// round 7
// baseline (speedup 1.0000x reference)
#include <cuda_runtime.h>

// DRP_LAYER: 2D DRP-FDTD, 3 steps, B=2, N=2048.
// R7: scatter-form stencils. Iterate input rows once per thread, accumulate
// into a statically-indexed register strip of outputs. float2 loads on
// even-stride padded E/Hy ping-pong buffers (R6 infrastructure).

#define NN   2048
#define BB   2
#define CFLc 0.35f

#define ES   (NN + 1)              // 2049 d_out E stride (odd -> scalar stores)
#define HXS  (NN)                  // 2048
#define HYS  (NN - 1)              // 2047 d_out Hy stride (odd -> scalar stores)
#define ESZ  ((NN + 1) * (NN + 1))
#define HXSZ ((NN - 1) * NN)
#define HYSZ (NN * (NN - 1))

#define PE   2052                  // padded E stride (even)
#define PHY  2048                  // padded Hy stride

__device__ __align__(16) float g_EpadA[BB * (NN + 1) * PE];
__device__ __align__(16) float g_EpadB[BB * (NN + 1) * PE];
__device__ __align__(16) float g_HyA[BB * NN * PHY];
__device__ __align__(16) float g_HyB[BB * NN * PHY];

__device__ float g_coef[2];   // [0]=u = 0.25*beta - 0.1*gamma, [1]=delta

__global__ void coef_kernel(const float* __restrict__ beta,
                            const float* __restrict__ delta,
                            const float* __restrict__ gamma) {
    g_coef[0] = 0.25f * beta[0] - 0.1f * gamma[0];
    g_coef[1] = delta[0];
}

__global__ void repackE_kernel(const float* __restrict__ E0) {
    int idx = blockIdx.x * blockDim.x + threadIdx.x;
    const int tot = BB * ES * ES;
    if (idx >= tot) return;
    int b = idx / (ES * ES);
    int r = (idx / ES) % ES;
    int c = idx % ES;
    g_EpadA[((size_t)b * ES + r) * PE + c] = E0[idx];
}

__global__ void repackHy_kernel(const float* __restrict__ Hy0) {
    int idx = blockIdx.x * blockDim.x + threadIdx.x;
    const int tot = BB * NN * HYS;
    if (idx >= tot) return;
    int b = idx / (NN * HYS);
    int r = (idx / HYS) % NN;
    int c = idx % HYS;
    g_HyA[((size_t)b * NN + r) * PHY + c] = Hy0[idx];
}

#define KF0 (-11.0f/6.0f)
#define KF1 (3.0f)
#define KF2 (-1.5f)
#define KF3 (1.0f/3.0f)
#define KB0 (-1.0f/3.0f)
#define KB1 (1.5f)
#define KB2 (-3.0f)
#define KB3 (11.0f/6.0f)

#define LDROW(dst, base, off, n) do {                                      \
    const float2* _p = reinterpret_cast<const float2*>((base) + (off));    \
    _Pragma("unroll")                                                      \
    for (int _k = 0; _k < (n); _k++) {                                     \
        float2 _v = _p[_k]; (dst)[2*_k] = _v.x; (dst)[2*_k+1] = _v.y;      \
    } } while (0)

// ---------------------------------------------------------------------------
// Ampere: E_out = E + CFL*(s1 - s2).
// Block (64,2): thread = col pair j0 = jb+2tx, output strip of 16 rows at
// Rs = R0 + ty*16. Block tile: 128 cols x 32 rows.
// ---------------------------------------------------------------------------
#define AS 16   // amper strip height

__global__ __launch_bounds__(128, 6) void amper_kernel(
    const float* __restrict__ epad_in, const float* __restrict__ Hx,
    const float* __restrict__ hyp_in,
    float* __restrict__ eo_d, float* __restrict__ epad_out)
{
    const int jb = blockIdx.x * 128;
    const int Rs = blockIdx.y * 32 + threadIdx.y * AS;
    const int tx = threadIdx.x;
    const int j0 = jb + 2 * tx;
    const int b  = blockIdx.z;

    const float* __restrict__ ein = epad_in + (size_t)b * ES * PE;
    const float* __restrict__ hx  = Hx      + (size_t)b * HXSZ;
    const float* __restrict__ hyp = hyp_in  + (size_t)b * NN * PHY;
    float* __restrict__ eo  = eo_d     + (size_t)b * ESZ;
    float* __restrict__ epo = epad_out + (size_t)b * ES * PE;

    const float u  = g_coef[0];
    const float dl = g_coef[1];
    const float c01 = u + dl - 0.5f;
    const float c11 = -2.0f * dl;
    const float c21 = dl + 0.5f - u;
    const float cKF = c21 + KF0;
    const float cKB = u + KB3;

    const bool fast = (Rs >= 8) && (Rs + AS - 1 <= NN - 5) &&
                      (jb >= 128) && (jb + 127 <= NN - 5);

    if (fast) {
        float acc0[AS], acc1[AS];
#pragma unroll
        for (int o = 0; o < AS; o++) { acc0[o] = 0.0f; acc1[o] = 0.0f; }

        // ---- Hy contributions (s1, added). Row y=Rs+yr contributes to
        // outputs o = yr-1 (yp1), yr (y0), yr+1 (ym1), yr+2 (ym2).
        // Buffer yv[k] = Hy(y, j0-6+k); Hy(y, j0+q+d) -> yv[q+d+6].
#pragma unroll
        for (int yr = -2; yr <= AS; yr++) {
            float yv[12];
            LDROW(yv, hyp, (Rs + yr) * PHY + (j0 - 6), 6);
#pragma unroll
            for (int q = 0; q < 2; q++) {
                float* acc = q ? acc1 : acc0;
                if (yr - 1 >= 0 && yr - 1 < AS)
                    acc[yr-1] += -u * yv[4+q] + u * yv[6+q];
                if (yr >= 0 && yr < AS)
                    acc[yr] += KB0 * yv[1+q] + KB1 * yv[2+q] + KB2 * yv[3+q]
                             + cKB * yv[4+q] - u * yv[6+q];
                if (yr + 1 >= 0 && yr + 1 < AS)
                    acc[yr+1] += c01 * yv[4+q] + c11 * yv[5+q] + cKF * yv[6+q]
                               + KF1 * yv[7+q] + KF2 * yv[8+q] + KF3 * yv[9+q];
                if (yr + 2 >= 0 && yr + 2 < AS)
                    acc[yr+2] += -u * yv[4+q] + u * yv[6+q];
            }
        }

        // ---- Hx contributions (s2, subtracted). Row x=Rs+xr contributes to
        // o = xr+5 (xm5) ... o = xr-3 (xp3).
        // Buffer xv[k] = Hx(x, j0-2+k); Hx(x, j0+q+d) -> xv[q+d+2].
#pragma unroll
        for (int xr = -5; xr <= AS + 2; xr++) {
            float xv[6];
            LDROW(xv, hx, (Rs + xr) * HXS + (j0 - 2), 3);
#pragma unroll
            for (int q = 0; q < 2; q++) {
                float* acc = q ? acc1 : acc0;
                if (xr + 5 >= 0 && xr + 5 < AS) acc[xr+5] -= KB0 * xv[2+q];
                if (xr + 4 >= 0 && xr + 4 < AS) acc[xr+4] -= KB1 * xv[2+q];
                if (xr + 3 >= 0 && xr + 3 < AS) acc[xr+3] -= KB2 * xv[2+q];
                if (xr + 2 >= 0 && xr + 2 < AS)
                    acc[xr+2] -= -u * xv[q] + c01 * xv[1+q] + cKB * xv[2+q] - u * xv[3+q];
                if (xr + 1 >= 0 && xr + 1 < AS) acc[xr+1] -= c11 * xv[1+q];
                if (xr >= 0 && xr < AS)
                    acc[xr] -= u * xv[q] + cKF * xv[1+q] - u * xv[2+q] + u * xv[3+q];
                if (xr - 1 >= 0 && xr - 1 < AS) acc[xr-1] -= KF1 * xv[1+q];
                if (xr - 2 >= 0 && xr - 2 < AS) acc[xr-2] -= KF2 * xv[1+q];
                if (xr - 3 >= 0 && xr - 3 < AS) acc[xr-3] -= KF3 * xv[1+q];
            }
        }

        // ---- epilogue ----
#pragma unroll
        for (int o = 0; o < AS; o++) {
            const int r = Rs + o;
            float2 ep = *reinterpret_cast<const float2*>(ein + (size_t)r * PE + j0);
            const float o0 = ep.x + CFLc * acc0[o];
            const float o1 = ep.y + CFLc * acc1[o];
            eo[(size_t)r * ES + j0]     = o0;
            eo[(size_t)r * ES + j0 + 1] = o1;
            *reinterpret_cast<float2*>(epo + (size_t)r * PE + j0) = make_float2(o0, o1);
        }
        return;
    }

    // ---- generic path (edge strips) ----
#define HXg(rr,cc) hx[(rr) * HXS + (cc)]
#define HYg(rr,cc) hyp[(rr) * PHY + (cc)]
    for (int o = 0; o < AS; o++) {
        const int i = Rs + o;
        if (i > NN) break;
#pragma unroll
        for (int q = 0; q < 2; q++) {
            const int j = j0 + q;
            if (j > NN) break;

            const bool iin = (i >= 2) && (i <= NN - 2);
            const bool jin = (j >= 2) && (j <= NN - 2);

            float s1 = 0.0f;
            if (iin && jin) {
                s1 += -u  * HYg(i-2, j-2) + u   * HYg(i-2, j)
                    + c01 * HYg(i-1, j-2) + c11 * HYg(i-1, j-1) + c21 * HYg(i-1, j)
                    + u   * HYg(i  , j-2) - u   * HYg(i  , j)
                    - u   * HYg(i+1, j-2) + u   * HYg(i+1, j);
            }
            if (i >= 1 && j <= NN - 5)
                s1 += KF0*HYg(i-1, j) + KF1*HYg(i-1, j+1) + KF2*HYg(i-1, j+2) + KF3*HYg(i-1, j+3);
            if (i <= NN - 1 && j >= 5)
                s1 += KB0*HYg(i, j-5) + KB1*HYg(i, j-4) + KB2*HYg(i, j-3) + KB3*HYg(i, j-2);
            if (iin && (j == 1 || j == 2))
                s1 += -HYg(i-1, j-1) + 3.0f*HYg(i-1, j) - 3.0f*HYg(i-1, j+1) + HYg(i-1, j+2);
            if (iin && (j == NN-2 || j == NN-1))
                s1 += HYg(i, j-4) - 3.0f*HYg(i, j-3) + 3.0f*HYg(i, j-2) - HYg(i, j-1);

            float s2 = 0.0f;
            if (iin && jin) {
                s2 += -u  * HXg(i-2, j-2) + c01 * HXg(i-2, j-1) + u * HXg(i-2, j) - u * HXg(i-2, j+1)
                    + c11 * HXg(i-1, j-1)
                    + u   * HXg(i  , j-2) + c21 * HXg(i  , j-1) - u * HXg(i  , j) + u * HXg(i  , j+1);
            }
            if (i <= NN - 5 && j >= 1)
                s2 += KF0*HXg(i, j-1) + KF1*HXg(i+1, j-1) + KF2*HXg(i+2, j-1) + KF3*HXg(i+3, j-1);
            if (i >= 5 && j <= NN - 1)
                s2 += KB0*HXg(i-5, j) + KB1*HXg(i-4, j) + KB2*HXg(i-3, j) + KB3*HXg(i-2, j);
            if ((i == 1 || i == 2) && jin)
                s2 += -HXg(i-1, j-1) + 3.0f*HXg(i, j-1) - 3.0f*HXg(i+1, j-1) + HXg(i+2, j-1);
            if ((i == NN-2 || i == NN-1) && jin)
                s2 += HXg(i-4, j) - 3.0f*HXg(i-3, j) + 3.0f*HXg(i-2, j) - HXg(i-1, j);

            const float val = ein[(size_t)i * PE + j] + CFLc * (s1 - s2);
            eo[(size_t)i * ES + j] = val;
            epo[(size_t)i * PE + j] = val;
        }
    }
#undef HXg
#undef HYg
}

// ---------------------------------------------------------------------------
// Faraday: Hx_out = Hx - CFL*s3 ; Hy_out = Hy + CFL*s4
// Block (64,2): thread = col pair j0, output strip of 8 rows at
// Rs = R0 + ty*8. Block tile: 128 cols x 16 rows.
// ---------------------------------------------------------------------------
#define FS 8    // faraday strip height

__global__ __launch_bounds__(128, 6) void faraday_kernel(
    const float* __restrict__ epad_in, const float* __restrict__ Hx,
    const float* __restrict__ hyp_in,
    float* __restrict__ hxo_d, float* __restrict__ hyo_d,
    float* __restrict__ hyp_out)
{
    const int jb = blockIdx.x * 128;
    const int Rs = blockIdx.y * 16 + threadIdx.y * FS;
    const int tx = threadIdx.x;
    const int j0 = jb + 2 * tx;
    const int b  = blockIdx.z;

    const float* __restrict__ ein = epad_in + (size_t)b * ES * PE;
    const float* __restrict__ hx  = Hx      + (size_t)b * HXSZ;
    const float* __restrict__ hyp = hyp_in  + (size_t)b * NN * PHY;
    float* __restrict__ hxo = hxo_d   + (size_t)b * HXSZ;
    float* __restrict__ hyo = hyo_d   + (size_t)b * HYSZ;
    float* __restrict__ hpo = hyp_out + (size_t)b * NN * PHY;

    const float u  = g_coef[0];
    const float dl = g_coef[1];
    const float c01 = u + dl - 0.5f;
    const float c11 = -2.0f * dl;
    const float c21 = dl + 0.5f - u;

    const bool fast = (Rs >= 8) && (Rs + FS - 1 <= NN - 4) &&
                      (jb >= 128) && (jb + 127 <= NN - 4);

    if (fast) {
        float a30[FS], a31[FS], a40[FS], a41[FS];
#pragma unroll
        for (int o = 0; o < FS; o++) { a30[o]=0.f; a31[o]=0.f; a40[o]=0.f; a41[o]=0.f; }

        // E row er=Rs+er_rel contributes to o = er+1 (em1), er (e0),
        // er-1 (ep1), er-2 (ep2), er-3 (ep3).
        // Buffer ev[k] = E(er, j0-2+k); E(er, j0+q+d) -> ev[q+d+2].
#pragma unroll
        for (int er = -1; er <= FS + 2; er++) {
            float ev[8];
            LDROW(ev, ein, (Rs + er) * PE + (j0 - 2), 4);
#pragma unroll
            for (int q = 0; q < 2; q++) {
                float* a3 = q ? a31 : a30;
                float* a4 = q ? a41 : a40;
                if (er + 1 >= 0 && er + 1 < FS) {        // em1
                    a3[er+1] += 0.5f * ev[q+3];
                    a4[er+1] += -u * ev[q+2] + u * ev[q+4];
                }
                if (er >= 0 && er < FS) {                // e0
                    a3[er] += -u * ev[q+1] + c01 * ev[q+2] + (u - 2.0f) * ev[q+3] - u * ev[q+4];
                    a4[er] += c01 * ev[q+2] + (c11 - 1.5f) * ev[q+3]
                            + (c21 + 2.0f) * ev[q+4] - 0.5f * ev[q+5];
                }
                if (er - 1 >= 0 && er - 1 < FS) {        // ep1
                    a3[er-1] += (c11 - 1.5f) * ev[q+2] + 1.5f * ev[q+3];
                    a4[er-1] += 0.5f * ev[q+1] + (u - 2.0f) * ev[q+2]
                              + 1.5f * ev[q+3] - u * ev[q+4];
                }
                if (er - 2 >= 0 && er - 2 < FS) {        // ep2
                    a3[er-2] += u * ev[q+1] + (c21 + 2.0f) * ev[q+2]
                              - u * ev[q+3] + u * ev[q+4];
                    a4[er-2] += -u * ev[q+2] + u * ev[q+4];
                }
                if (er - 3 >= 0 && er - 3 < FS)          // ep3
                    a3[er-3] += -0.5f * ev[q+2];
            }
        }

#pragma unroll
        for (int o = 0; o < FS; o++) {
            const int i = Rs + o;
            float2 hxp = *reinterpret_cast<const float2*>(hx  + (size_t)i * HXS + j0);
            float2 hyv = *reinterpret_cast<const float2*>(hyp + (size_t)i * PHY + j0);
            const float x0 = hxp.x - CFLc * a30[o];
            const float x1 = hxp.y - CFLc * a31[o];
            const float y0 = hyv.x + CFLc * a40[o];
            const float y1 = hyv.y + CFLc * a41[o];
            *reinterpret_cast<float2*>(hxo + (size_t)i * HXS + j0) = make_float2(x0, x1);
            hyo[(size_t)i * HYS + j0]     = y0;
            hyo[(size_t)i * HYS + j0 + 1] = y1;
            *reinterpret_cast<float2*>(hpo + (size_t)i * PHY + j0) = make_float2(y0, y1);
        }
        return;
    }

    // ---- generic path (edge strips) ----
#define EEg(rr,cc) ein[(rr) * PE + (cc)]
    for (int o = 0; o < FS; o++) {
        const int i = Rs + o;
        if (i >= NN) break;
#pragma unroll
        for (int q = 0; q < 2; q++) {
            const int j = j0 + q;
            if (j >= NN) break;

            if (i <= NN - 2) {
                float s3 = 0.0f;
                if (j >= 1 && j <= NN - 2) {
                    s3 += -u  * EEg(i  , j-1) + c01 * EEg(i  , j) + u * EEg(i  , j+1) - u * EEg(i  , j+2)
                        + c11 * EEg(i+1, j)
                        + u   * EEg(i+2, j-1) + c21 * EEg(i+2, j) - u * EEg(i+2, j+1) + u * EEg(i+2, j+2);
                }
                if (i <= NN - 4)
                    s3 += -1.5f * EEg(i+1, j) + 2.0f * EEg(i+2, j) - 0.5f * EEg(i+3, j);
                if (i >= 2)
                    s3 +=  0.5f * EEg(i-1, j+1) - 2.0f * EEg(i, j+1) + 1.5f * EEg(i+1, j+1);
                hxo[(size_t)i * HXS + j] = hx[(size_t)i * HXS + j] - CFLc * s3;
            }

            if (j <= NN - 2) {
                float s4 = 0.0f;
                if (i >= 1 && i <= NN - 2) {
                    s4 += -u  * EEg(i-1, j) + u * EEg(i-1, j+2)
                        + c01 * EEg(i  , j) + c11 * EEg(i, j+1) + c21 * EEg(i, j+2)
                        + u   * EEg(i+1, j) - u * EEg(i+1, j+2)
                        - u   * EEg(i+2, j) + u * EEg(i+2, j+2);
                }
                if (j <= NN - 4)
                    s4 += -1.5f * EEg(i, j+1) + 2.0f * EEg(i, j+2) - 0.5f * EEg(i, j+3);
                if (j >= 2)
                    s4 +=  0.5f * EEg(i+1, j-1) - 2.0f * EEg(i+1, j) + 1.5f * EEg(i+1, j+1);
                const float val = hyp[(size_t)i * PHY + j] + CFLc * s4;
                hyo[(size_t)i * HYS + j] = val;
                hpo[(size_t)i * PHY + j] = val;
            }
        }
    }
#undef EEg
}

// ---------------------------------------------------------------------------
extern "C" void kernel_launch(void* const* d_in, const int* in_sizes, int n_in,
                              void* d_out, int out_size)
{
    const float* E0    = (const float*)d_in[0];
    const float* Hx0   = (const float*)d_in[1];
    const float* Hy0   = (const float*)d_in[2];
    const float* beta  = (const float*)d_in[3];
    const float* delta = (const float*)d_in[4];
    const float* gamma = (const float*)d_in[5];

    float* out = (float*)d_out;
    const size_t esz  = (size_t)BB * ESZ;
    const size_t hxsz = (size_t)BB * HXSZ;
    const size_t hysz = (size_t)BB * HYSZ;

    float* E2  = out;
    float* Hx2 = E2  + esz;
    float* Hy2 = Hx2 + hxsz;
    float* E3  = Hy2 + hysz;
    float* Hx3 = E3  + esz;
    float* Hy3 = Hx3 + hxsz;
    float* E4  = Hy3 + hysz;
    float* Hx4 = E4  + esz;
    float* Hy4 = Hx4 + hxsz;

    float *EA, *EB, *HA, *HB;
    cudaGetSymbolAddress((void**)&EA, g_EpadA);
    cudaGetSymbolAddress((void**)&EB, g_EpadB);
    cudaGetSymbolAddress((void**)&HA, g_HyA);
    cudaGetSymbolAddress((void**)&HB, g_HyB);

    coef_kernel<<<1, 1>>>(beta, delta, gamma);

    const int eTot  = BB * ES * ES;
    const int hyTot = BB * NN * HYS;
    repackE_kernel <<<(eTot  + 255) / 256, 256>>>(E0);
    repackHy_kernel<<<(hyTot + 255) / 256, 256>>>(Hy0);

    dim3 blk(64, 2, 1);
    dim3 gA(17, (NN + 1 + 31) / 32, BB);   // 17 x 65 x 2, 32 rows/block
    dim3 gF(16, NN / 16, BB);              // 16 x 128 x 2, 16 rows/block

    // step 1
    amper_kernel  <<<gA, blk>>>(EA, Hx0, HA, E2, EB);
    faraday_kernel<<<gF, blk>>>(EB, Hx0, HA, Hx2, Hy2, HB);
    // step 2
    amper_kernel  <<<gA, blk>>>(EB, Hx2, HB, E3, EA);
    faraday_kernel<<<gF, blk>>>(EA, Hx2, HB, Hx3, Hy3, HA);
    // step 3
    amper_kernel  <<<gA, blk>>>(EA, Hx3, HA, E4, EB);
    faraday_kernel<<<gF, blk>>>(EB, Hx3, HA, Hx4, Hy4, HB);
}

// round 8
// speedup vs baseline: 1.1841x; 1.1841x over previous
#include <cuda_runtime.h>

// DRP_LAYER: 2D DRP-FDTD, 3 steps, B=2, N=2048.
// R8: R6 float2 gather kernels + 2-row coarsening with merged row buffers.

#define NN   2048
#define BB   2
#define CFLc 0.35f

#define ES   (NN + 1)
#define HXS  (NN)
#define HYS  (NN - 1)
#define ESZ  ((NN + 1) * (NN + 1))
#define HXSZ ((NN - 1) * NN)
#define HYSZ (NN * (NN - 1))

#define PE   2052
#define PHY  2048

__device__ __align__(16) float g_EpadA[BB * (NN + 1) * PE];
__device__ __align__(16) float g_EpadB[BB * (NN + 1) * PE];
__device__ __align__(16) float g_HyA[BB * NN * PHY];
__device__ __align__(16) float g_HyB[BB * NN * PHY];

__device__ float g_coef[2];

__global__ void coef_kernel(const float* __restrict__ beta,
                            const float* __restrict__ delta,
                            const float* __restrict__ gamma) {
    g_coef[0] = 0.25f * beta[0] - 0.1f * gamma[0];
    g_coef[1] = delta[0];
}

__global__ void repackE_kernel(const float* __restrict__ E0) {
    int idx = blockIdx.x * blockDim.x + threadIdx.x;
    const int tot = BB * ES * ES;
    if (idx >= tot) return;
    int b = idx / (ES * ES);
    int r = (idx / ES) % ES;
    int c = idx % ES;
    g_EpadA[((size_t)b * ES + r) * PE + c] = E0[idx];
}

__global__ void repackHy_kernel(const float* __restrict__ Hy0) {
    int idx = blockIdx.x * blockDim.x + threadIdx.x;
    const int tot = BB * NN * HYS;
    if (idx >= tot) return;
    int b = idx / (NN * HYS);
    int r = (idx / HYS) % NN;
    int c = idx % HYS;
    g_HyA[((size_t)b * NN + r) * PHY + c] = Hy0[idx];
}

#define KF0 (-11.0f/6.0f)
#define KF1 (3.0f)
#define KF2 (-1.5f)
#define KF3 (1.0f/3.0f)
#define KB0 (-1.0f/3.0f)
#define KB1 (1.5f)
#define KB2 (-3.0f)
#define KB3 (11.0f/6.0f)

#define LDROW(dst, base, off, n) do {                                      \
    const float2* _p = reinterpret_cast<const float2*>((base) + (off));    \
    _Pragma("unroll")                                                      \
    for (int _k = 0; _k < (n); _k++) {                                     \
        float2 _v = _p[_k]; (dst)[2*_k] = _v.x; (dst)[2*_k+1] = _v.y;      \
    } } while (0)

// ---------------------------------------------------------------------------
// Ampere: E_out = E + CFL*(s1 - s2).
// Block (64,4): thread = col pair j0 = jb+2tx, rows r = R0+2ty, r+1.
// Block tile: 128 cols x 8 rows.
// ---------------------------------------------------------------------------
__global__ __launch_bounds__(256, 3) void amper_kernel(
    const float* __restrict__ epad_in, const float* __restrict__ Hx,
    const float* __restrict__ hyp_in,
    float* __restrict__ eo_d, float* __restrict__ epad_out)
{
    const int jb = blockIdx.x * 128;
    const int R0 = blockIdx.y * 8;
    const int tx = threadIdx.x;
    const int r  = R0 + threadIdx.y * 2;
    const int j0 = jb + 2 * tx;
    const int b  = blockIdx.z;

    const float* __restrict__ ein = epad_in + (size_t)b * ES * PE;
    const float* __restrict__ hx  = Hx      + (size_t)b * HXSZ;
    const float* __restrict__ hyp = hyp_in  + (size_t)b * NN * PHY;
    float* __restrict__ eo  = eo_d     + (size_t)b * ESZ;
    float* __restrict__ epo = epad_out + (size_t)b * ES * PE;

    const float u  = g_coef[0];
    const float dl = g_coef[1];
    const float c01 = u + dl - 0.5f;
    const float c11 = -2.0f * dl;
    const float c21 = dl + 0.5f - u;
    const float cKF = c21 + KF0;
    const float cKB = u + KB3;

    const bool fast = (R0 >= 8) && (R0 + 7 <= NN - 5) &&
                      (jb >= 128) && (jb + 127 <= NN - 5);

    if (fast) {
        float acc[2][2];

        // ---- Hy rows r-2..r+2, merged spans ----
        {
            float hm2[4], hm1[8], h0[12], hp1[8], hp2[4];
            LDROW(hm2, hyp, (r-2) * PHY + (j0-2), 2);   // origin j0-2
            LDROW(hm1, hyp, (r-1) * PHY + (j0-2), 4);   // origin j0-2
            LDROW(h0 , hyp, (r  ) * PHY + (j0-6), 6);   // origin j0-6
            LDROW(hp1, hyp, (r+1) * PHY + (j0-6), 4);   // origin j0-6
            LDROW(hp2, hyp, (r+2) * PHY + (j0-2), 2);   // origin j0-2
#pragma unroll
            for (int q = 0; q < 2; q++) {
                // output row r
                acc[0][q] =
                      -u * hm2[q] + u * hm2[q+2]
                    + c01 * hm1[q] + c11 * hm1[q+1] + cKF * hm1[q+2]
                    + KF1 * hm1[q+3] + KF2 * hm1[q+4] + KF3 * hm1[q+5]
                    + KB0 * h0[q+1] + KB1 * h0[q+2] + KB2 * h0[q+3]
                    + cKB * h0[q+4] - u * h0[q+6]
                    - u * hp1[q+4] + u * hp1[q+6];
                // output row r+1
                acc[1][q] =
                      -u * hm1[q] + u * hm1[q+2]
                    + c01 * h0[q+4] + c11 * h0[q+5] + cKF * h0[q+6]
                    + KF1 * h0[q+7] + KF2 * h0[q+8] + KF3 * h0[q+9]
                    + KB0 * hp1[q+1] + KB1 * hp1[q+2] + KB2 * hp1[q+3]
                    + cKB * hp1[q+4] - u * hp1[q+6]
                    - u * hp2[q] + u * hp2[q+2];
            }
        }

        // ---- Hx rows r-5..r+4, merged spans ----
        {
            float a5[2], a4[2], a3[2], a2[6], a1[6], a0[6], b1[6], b2[4], b3[4], b4[4];
            LDROW(a5, hx, (r-5) * HXS + j0,     1);     // origin j0
            LDROW(a4, hx, (r-4) * HXS + j0,     1);     // origin j0
            LDROW(a3, hx, (r-3) * HXS + j0,     1);     // origin j0
            LDROW(a2, hx, (r-2) * HXS + (j0-2), 3);     // origin j0-2
            LDROW(a1, hx, (r-1) * HXS + (j0-2), 3);     // origin j0-2
            LDROW(a0, hx, (r  ) * HXS + (j0-2), 3);     // origin j0-2
            LDROW(b1, hx, (r+1) * HXS + (j0-2), 3);     // origin j0-2
            LDROW(b2, hx, (r+2) * HXS + (j0-2), 2);     // origin j0-2
            LDROW(b3, hx, (r+3) * HXS + (j0-2), 2);     // origin j0-2
            LDROW(b4, hx, (r+4) * HXS + (j0-2), 2);     // origin j0-2
#pragma unroll
            for (int q = 0; q < 2; q++) {
                // output row r
                acc[0][q] -=
                      KB0 * a5[q] + KB1 * a4[q] + KB2 * a3[q]
                    - u * a2[q] + c01 * a2[q+1] + cKB * a2[q+2] - u * a2[q+3]
                    + c11 * a1[q+1]
                    + u * a0[q] + cKF * a0[q+1] - u * a0[q+2] + u * a0[q+3]
                    + KF1 * b1[q+1] + KF2 * b2[q+1] + KF3 * b3[q+1];
                // output row r+1
                acc[1][q] -=
                      KB0 * a4[q] + KB1 * a3[q] + KB2 * a2[q+2]
                    - u * a1[q] + c01 * a1[q+1] + cKB * a1[q+2] - u * a1[q+3]
                    + c11 * a0[q+1]
                    + u * b1[q] + cKF * b1[q+1] - u * b1[q+2] + u * b1[q+3]
                    + KF1 * b2[q+1] + KF2 * b3[q+1] + KF3 * b4[q+1];
            }
        }

        // ---- epilogue ----
#pragma unroll
        for (int rr = 0; rr < 2; rr++) {
            const int i = r + rr;
            float2 ep = *reinterpret_cast<const float2*>(ein + (size_t)i * PE + j0);
            const float o0 = ep.x + CFLc * acc[rr][0];
            const float o1 = ep.y + CFLc * acc[rr][1];
            eo[(size_t)i * ES + j0]     = o0;
            eo[(size_t)i * ES + j0 + 1] = o1;
            *reinterpret_cast<float2*>(epo + (size_t)i * PE + j0) = make_float2(o0, o1);
        }
        return;
    }

    // ---- generic path (edges) ----
#define HXg(rr,cc) hx[(rr) * HXS + (cc)]
#define HYg(rr,cc) hyp[(rr) * PHY + (cc)]
    for (int rr = 0; rr < 2; rr++) {
        const int i = r + rr;
        if (i > NN) break;
#pragma unroll
        for (int q = 0; q < 2; q++) {
            const int j = j0 + q;
            if (j > NN) break;

            const bool iin = (i >= 2) && (i <= NN - 2);
            const bool jin = (j >= 2) && (j <= NN - 2);

            float s1 = 0.0f;
            if (iin && jin) {
                s1 += -u  * HYg(i-2, j-2) + u   * HYg(i-2, j)
                    + c01 * HYg(i-1, j-2) + c11 * HYg(i-1, j-1) + c21 * HYg(i-1, j)
                    + u   * HYg(i  , j-2) - u   * HYg(i  , j)
                    - u   * HYg(i+1, j-2) + u   * HYg(i+1, j);
            }
            if (i >= 1 && j <= NN - 5)
                s1 += KF0*HYg(i-1, j) + KF1*HYg(i-1, j+1) + KF2*HYg(i-1, j+2) + KF3*HYg(i-1, j+3);
            if (i <= NN - 1 && j >= 5)
                s1 += KB0*HYg(i, j-5) + KB1*HYg(i, j-4) + KB2*HYg(i, j-3) + KB3*HYg(i, j-2);
            if (iin && (j == 1 || j == 2))
                s1 += -HYg(i-1, j-1) + 3.0f*HYg(i-1, j) - 3.0f*HYg(i-1, j+1) + HYg(i-1, j+2);
            if (iin && (j == NN-2 || j == NN-1))
                s1 += HYg(i, j-4) - 3.0f*HYg(i, j-3) + 3.0f*HYg(i, j-2) - HYg(i, j-1);

            float s2 = 0.0f;
            if (iin && jin) {
                s2 += -u  * HXg(i-2, j-2) + c01 * HXg(i-2, j-1) + u * HXg(i-2, j) - u * HXg(i-2, j+1)
                    + c11 * HXg(i-1, j-1)
                    + u   * HXg(i  , j-2) + c21 * HXg(i  , j-1) - u * HXg(i  , j) + u * HXg(i  , j+1);
            }
            if (i <= NN - 5 && j >= 1)
                s2 += KF0*HXg(i, j-1) + KF1*HXg(i+1, j-1) + KF2*HXg(i+2, j-1) + KF3*HXg(i+3, j-1);
            if (i >= 5 && j <= NN - 1)
                s2 += KB0*HXg(i-5, j) + KB1*HXg(i-4, j) + KB2*HXg(i-3, j) + KB3*HXg(i-2, j);
            if ((i == 1 || i == 2) && jin)
                s2 += -HXg(i-1, j-1) + 3.0f*HXg(i, j-1) - 3.0f*HXg(i+1, j-1) + HXg(i+2, j-1);
            if ((i == NN-2 || i == NN-1) && jin)
                s2 += HXg(i-4, j) - 3.0f*HXg(i-3, j) + 3.0f*HXg(i-2, j) - HXg(i-1, j);

            const float val = ein[(size_t)i * PE + j] + CFLc * (s1 - s2);
            eo[(size_t)i * ES + j] = val;
            epo[(size_t)i * PE + j] = val;
        }
    }
#undef HXg
#undef HYg
}

// ---------------------------------------------------------------------------
// Faraday: Hx_out = Hx - CFL*s3 ; Hy_out = Hy + CFL*s4
// Block (64,4): thread = col pair j0, rows i = R0+2ty, i+1.
// ---------------------------------------------------------------------------
__global__ __launch_bounds__(256, 4) void faraday_kernel(
    const float* __restrict__ epad_in, const float* __restrict__ Hx,
    const float* __restrict__ hyp_in,
    float* __restrict__ hxo_d, float* __restrict__ hyo_d,
    float* __restrict__ hyp_out)
{
    const int jb = blockIdx.x * 128;
    const int R0 = blockIdx.y * 8;
    const int tx = threadIdx.x;
    const int i0 = R0 + threadIdx.y * 2;
    const int j0 = jb + 2 * tx;
    const int b  = blockIdx.z;

    const float* __restrict__ ein = epad_in + (size_t)b * ES * PE;
    const float* __restrict__ hx  = Hx      + (size_t)b * HXSZ;
    const float* __restrict__ hyp = hyp_in  + (size_t)b * NN * PHY;
    float* __restrict__ hxo = hxo_d   + (size_t)b * HXSZ;
    float* __restrict__ hyo = hyo_d   + (size_t)b * HYSZ;
    float* __restrict__ hpo = hyp_out + (size_t)b * NN * PHY;

    const float u  = g_coef[0];
    const float dl = g_coef[1];
    const float c01 = u + dl - 0.5f;
    const float c11 = -2.0f * dl;
    const float c21 = dl + 0.5f - u;

    const bool fast = (R0 >= 8) && (R0 + 7 <= NN - 4) &&
                      (jb >= 128) && (jb + 127 <= NN - 4);

    if (fast) {
        // E rows i0-1..i0+4, merged spans
        float fm1[4], f0[8], f1[8], f2[6], f3[6], f4[2];
        LDROW(fm1, ein, (i0-1) * PE + j0,     2);   // origin j0
        LDROW(f0 , ein, (i0  ) * PE + (j0-2), 4);   // origin j0-2
        LDROW(f1 , ein, (i0+1) * PE + (j0-2), 4);   // origin j0-2
        LDROW(f2 , ein, (i0+2) * PE + (j0-2), 3);   // origin j0-2
        LDROW(f3 , ein, (i0+3) * PE + (j0-2), 3);   // origin j0-2
        LDROW(f4 , ein, (i0+4) * PE + j0,     1);   // origin j0

        float s3v[2][2], s4v[2][2];
#pragma unroll
        for (int q = 0; q < 2; q++) {
            // output row i0
            s3v[0][q] = 0.5f * fm1[q+1]
                      - u * f0[q+1] + c01 * f0[q+2] + (u - 2.0f) * f0[q+3] - u * f0[q+4]
                      + (c11 - 1.5f) * f1[q+2] + 1.5f * f1[q+3]
                      + u * f2[q+1] + (c21 + 2.0f) * f2[q+2] - u * f2[q+3] + u * f2[q+4]
                      - 0.5f * f3[q+2];
            s4v[0][q] = -u * fm1[q] + u * fm1[q+2]
                      + c01 * f0[q+2] + (c11 - 1.5f) * f0[q+3]
                      + (c21 + 2.0f) * f0[q+4] - 0.5f * f0[q+5]
                      + 0.5f * f1[q+1] + (u - 2.0f) * f1[q+2] + 1.5f * f1[q+3] - u * f1[q+4]
                      - u * f2[q+2] + u * f2[q+4];
            // output row i0+1
            s3v[1][q] = 0.5f * f0[q+3]
                      - u * f1[q+1] + c01 * f1[q+2] + (u - 2.0f) * f1[q+3] - u * f1[q+4]
                      + (c11 - 1.5f) * f2[q+2] + 1.5f * f2[q+3]
                      + u * f3[q+1] + (c21 + 2.0f) * f3[q+2] - u * f3[q+3] + u * f3[q+4]
                      - 0.5f * f4[q];
            s4v[1][q] = -u * f0[q+2] + u * f0[q+4]
                      + c01 * f1[q+2] + (c11 - 1.5f) * f1[q+3]
                      + (c21 + 2.0f) * f1[q+4] - 0.5f * f1[q+5]
                      + 0.5f * f2[q+1] + (u - 2.0f) * f2[q+2] + 1.5f * f2[q+3] - u * f2[q+4]
                      - u * f3[q+2] + u * f3[q+4];
        }

#pragma unroll
        for (int rr = 0; rr < 2; rr++) {
            const int i = i0 + rr;
            float2 hxp = *reinterpret_cast<const float2*>(hx  + (size_t)i * HXS + j0);
            float2 hyv = *reinterpret_cast<const float2*>(hyp + (size_t)i * PHY + j0);
            const float x0 = hxp.x - CFLc * s3v[rr][0];
            const float x1 = hxp.y - CFLc * s3v[rr][1];
            const float y0 = hyv.x + CFLc * s4v[rr][0];
            const float y1 = hyv.y + CFLc * s4v[rr][1];
            *reinterpret_cast<float2*>(hxo + (size_t)i * HXS + j0) = make_float2(x0, x1);
            hyo[(size_t)i * HYS + j0]     = y0;
            hyo[(size_t)i * HYS + j0 + 1] = y1;
            *reinterpret_cast<float2*>(hpo + (size_t)i * PHY + j0) = make_float2(y0, y1);
        }
        return;
    }

    // ---- generic path (edges) ----
#define EEg(rr,cc) ein[(rr) * PE + (cc)]
    for (int rr = 0; rr < 2; rr++) {
        const int i = i0 + rr;
        if (i >= NN) break;
#pragma unroll
        for (int q = 0; q < 2; q++) {
            const int j = j0 + q;
            if (j >= NN) break;

            if (i <= NN - 2) {
                float s3 = 0.0f;
                if (j >= 1 && j <= NN - 2) {
                    s3 += -u  * EEg(i  , j-1) + c01 * EEg(i  , j) + u * EEg(i  , j+1) - u * EEg(i  , j+2)
                        + c11 * EEg(i+1, j)
                        + u   * EEg(i+2, j-1) + c21 * EEg(i+2, j) - u * EEg(i+2, j+1) + u * EEg(i+2, j+2);
                }
                if (i <= NN - 4)
                    s3 += -1.5f * EEg(i+1, j) + 2.0f * EEg(i+2, j) - 0.5f * EEg(i+3, j);
                if (i >= 2)
                    s3 +=  0.5f * EEg(i-1, j+1) - 2.0f * EEg(i, j+1) + 1.5f * EEg(i+1, j+1);
                hxo[(size_t)i * HXS + j] = hx[(size_t)i * HXS + j] - CFLc * s3;
            }

            if (j <= NN - 2) {
                float s4 = 0.0f;
                if (i >= 1 && i <= NN - 2) {
                    s4 += -u  * EEg(i-1, j) + u * EEg(i-1, j+2)
                        + c01 * EEg(i  , j) + c11 * EEg(i, j+1) + c21 * EEg(i, j+2)
                        + u   * EEg(i+1, j) - u * EEg(i+1, j+2)
                        - u   * EEg(i+2, j) + u * EEg(i+2, j+2);
                }
                if (j <= NN - 4)
                    s4 += -1.5f * EEg(i, j+1) + 2.0f * EEg(i, j+2) - 0.5f * EEg(i, j+3);
                if (j >= 2)
                    s4 +=  0.5f * EEg(i+1, j-1) - 2.0f * EEg(i+1, j) + 1.5f * EEg(i+1, j+1);
                const float val = hyp[(size_t)i * PHY + j] + CFLc * s4;
                hyo[(size_t)i * HYS + j] = val;
                hpo[(size_t)i * PHY + j] = val;
            }
        }
    }
#undef EEg
}

// ---------------------------------------------------------------------------
extern "C" void kernel_launch(void* const* d_in, const int* in_sizes, int n_in,
                              void* d_out, int out_size)
{
    const float* E0    = (const float*)d_in[0];
    const float* Hx0   = (const float*)d_in[1];
    const float* Hy0   = (const float*)d_in[2];
    const float* beta  = (const float*)d_in[3];
    const float* delta = (const float*)d_in[4];
    const float* gamma = (const float*)d_in[5];

    float* out = (float*)d_out;
    const size_t esz  = (size_t)BB * ESZ;
    const size_t hxsz = (size_t)BB * HXSZ;
    const size_t hysz = (size_t)BB * HYSZ;

    float* E2  = out;
    float* Hx2 = E2  + esz;
    float* Hy2 = Hx2 + hxsz;
    float* E3  = Hy2 + hysz;
    float* Hx3 = E3  + esz;
    float* Hy3 = Hx3 + hxsz;
    float* E4  = Hy3 + hysz;
    float* Hx4 = E4  + esz;
    float* Hy4 = Hx4 + hxsz;

    float *EA, *EB, *HA, *HB;
    cudaGetSymbolAddress((void**)&EA, g_EpadA);
    cudaGetSymbolAddress((void**)&EB, g_EpadB);
    cudaGetSymbolAddress((void**)&HA, g_HyA);
    cudaGetSymbolAddress((void**)&HB, g_HyB);

    coef_kernel<<<1, 1>>>(beta, delta, gamma);

    const int eTot  = BB * ES * ES;
    const int hyTot = BB * NN * HYS;
    repackE_kernel <<<(eTot  + 255) / 256, 256>>>(E0);
    repackHy_kernel<<<(hyTot + 255) / 256, 256>>>(Hy0);

    dim3 blk(64, 4, 1);
    dim3 gE(17, (ES + 7) / 8, BB);   // 17 x 257 x 2
    dim3 gF(16, NN / 8, BB);         // 16 x 256 x 2

    // step 1
    amper_kernel  <<<gE, blk>>>(EA, Hx0, HA, E2, EB);
    faraday_kernel<<<gF, blk>>>(EB, Hx0, HA, Hx2, Hy2, HB);
    // step 2
    amper_kernel  <<<gE, blk>>>(EB, Hx2, HB, E3, EA);
    faraday_kernel<<<gF, blk>>>(EA, Hx2, HB, Hx3, Hy3, HA);
    // step 3
    amper_kernel  <<<gE, blk>>>(EA, Hx3, HA, E4, EB);
    faraday_kernel<<<gF, blk>>>(EB, Hx3, HA, Hx4, Hy4, HB);
}

// round 9
// speedup vs baseline: 1.2746x; 1.0764x over previous
#include <cuda_runtime.h>

// DRP_LAYER: 2D DRP-FDTD, 3 steps, B=2, N=2048.
// R9: R8 + amper capped to 64 regs (__launch_bounds__(256,4)) for 4 blocks/SM.

#define NN   2048
#define BB   2
#define CFLc 0.35f

#define ES   (NN + 1)
#define HXS  (NN)
#define HYS  (NN - 1)
#define ESZ  ((NN + 1) * (NN + 1))
#define HXSZ ((NN - 1) * NN)
#define HYSZ (NN * (NN - 1))

#define PE   2052
#define PHY  2048

__device__ __align__(16) float g_EpadA[BB * (NN + 1) * PE];
__device__ __align__(16) float g_EpadB[BB * (NN + 1) * PE];
__device__ __align__(16) float g_HyA[BB * NN * PHY];
__device__ __align__(16) float g_HyB[BB * NN * PHY];

__device__ float g_coef[2];

__global__ void coef_kernel(const float* __restrict__ beta,
                            const float* __restrict__ delta,
                            const float* __restrict__ gamma) {
    g_coef[0] = 0.25f * beta[0] - 0.1f * gamma[0];
    g_coef[1] = delta[0];
}

__global__ void repackE_kernel(const float* __restrict__ E0) {
    int idx = blockIdx.x * blockDim.x + threadIdx.x;
    const int tot = BB * ES * ES;
    if (idx >= tot) return;
    int b = idx / (ES * ES);
    int r = (idx / ES) % ES;
    int c = idx % ES;
    g_EpadA[((size_t)b * ES + r) * PE + c] = E0[idx];
}

__global__ void repackHy_kernel(const float* __restrict__ Hy0) {
    int idx = blockIdx.x * blockDim.x + threadIdx.x;
    const int tot = BB * NN * HYS;
    if (idx >= tot) return;
    int b = idx / (NN * HYS);
    int r = (idx / HYS) % NN;
    int c = idx % HYS;
    g_HyA[((size_t)b * NN + r) * PHY + c] = Hy0[idx];
}

#define KF0 (-11.0f/6.0f)
#define KF1 (3.0f)
#define KF2 (-1.5f)
#define KF3 (1.0f/3.0f)
#define KB0 (-1.0f/3.0f)
#define KB1 (1.5f)
#define KB2 (-3.0f)
#define KB3 (11.0f/6.0f)

#define LDROW(dst, base, off, n) do {                                      \
    const float2* _p = reinterpret_cast<const float2*>((base) + (off));    \
    _Pragma("unroll")                                                      \
    for (int _k = 0; _k < (n); _k++) {                                     \
        float2 _v = _p[_k]; (dst)[2*_k] = _v.x; (dst)[2*_k+1] = _v.y;      \
    } } while (0)

// ---------------------------------------------------------------------------
// Ampere: E_out = E + CFL*(s1 - s2).
// Block (64,4): thread = col pair j0 = jb+2tx, rows r = R0+2ty, r+1.
// ---------------------------------------------------------------------------
__global__ __launch_bounds__(256, 4) void amper_kernel(
    const float* __restrict__ epad_in, const float* __restrict__ Hx,
    const float* __restrict__ hyp_in,
    float* __restrict__ eo_d, float* __restrict__ epad_out)
{
    const int jb = blockIdx.x * 128;
    const int R0 = blockIdx.y * 8;
    const int tx = threadIdx.x;
    const int r  = R0 + threadIdx.y * 2;
    const int j0 = jb + 2 * tx;
    const int b  = blockIdx.z;

    const float* __restrict__ ein = epad_in + (size_t)b * ES * PE;
    const float* __restrict__ hx  = Hx      + (size_t)b * HXSZ;
    const float* __restrict__ hyp = hyp_in  + (size_t)b * NN * PHY;
    float* __restrict__ eo  = eo_d     + (size_t)b * ESZ;
    float* __restrict__ epo = epad_out + (size_t)b * ES * PE;

    const float u  = g_coef[0];
    const float dl = g_coef[1];
    const float c01 = u + dl - 0.5f;
    const float c11 = -2.0f * dl;
    const float c21 = dl + 0.5f - u;
    const float cKF = c21 + KF0;
    const float cKB = u + KB3;

    const bool fast = (R0 >= 8) && (R0 + 7 <= NN - 5) &&
                      (jb >= 128) && (jb + 127 <= NN - 5);

    if (fast) {
        float acc[2][2];

        // ---- Hy rows r-2..r+2, merged spans ----
        {
            float hm2[4], hm1[8], h0[12], hp1[8], hp2[4];
            LDROW(hm2, hyp, (r-2) * PHY + (j0-2), 2);
            LDROW(hm1, hyp, (r-1) * PHY + (j0-2), 4);
            LDROW(h0 , hyp, (r  ) * PHY + (j0-6), 6);
            LDROW(hp1, hyp, (r+1) * PHY + (j0-6), 4);
            LDROW(hp2, hyp, (r+2) * PHY + (j0-2), 2);
#pragma unroll
            for (int q = 0; q < 2; q++) {
                acc[0][q] =
                      -u * hm2[q] + u * hm2[q+2]
                    + c01 * hm1[q] + c11 * hm1[q+1] + cKF * hm1[q+2]
                    + KF1 * hm1[q+3] + KF2 * hm1[q+4] + KF3 * hm1[q+5]
                    + KB0 * h0[q+1] + KB1 * h0[q+2] + KB2 * h0[q+3]
                    + cKB * h0[q+4] - u * h0[q+6]
                    - u * hp1[q+4] + u * hp1[q+6];
                acc[1][q] =
                      -u * hm1[q] + u * hm1[q+2]
                    + c01 * h0[q+4] + c11 * h0[q+5] + cKF * h0[q+6]
                    + KF1 * h0[q+7] + KF2 * h0[q+8] + KF3 * h0[q+9]
                    + KB0 * hp1[q+1] + KB1 * hp1[q+2] + KB2 * hp1[q+3]
                    + cKB * hp1[q+4] - u * hp1[q+6]
                    - u * hp2[q] + u * hp2[q+2];
            }
        }

        // ---- Hx rows r-5..r+4, merged spans ----
        {
            float a5[2], a4[2], a3[2], a2[6], a1[6], a0[6], b1[6], b2[4], b3[4], b4[4];
            LDROW(a5, hx, (r-5) * HXS + j0,     1);
            LDROW(a4, hx, (r-4) * HXS + j0,     1);
            LDROW(a3, hx, (r-3) * HXS + j0,     1);
            LDROW(a2, hx, (r-2) * HXS + (j0-2), 3);
            LDROW(a1, hx, (r-1) * HXS + (j0-2), 3);
            LDROW(a0, hx, (r  ) * HXS + (j0-2), 3);
            LDROW(b1, hx, (r+1) * HXS + (j0-2), 3);
            LDROW(b2, hx, (r+2) * HXS + (j0-2), 2);
            LDROW(b3, hx, (r+3) * HXS + (j0-2), 2);
            LDROW(b4, hx, (r+4) * HXS + (j0-2), 2);
#pragma unroll
            for (int q = 0; q < 2; q++) {
                acc[0][q] -=
                      KB0 * a5[q] + KB1 * a4[q] + KB2 * a3[q]
                    - u * a2[q] + c01 * a2[q+1] + cKB * a2[q+2] - u * a2[q+3]
                    + c11 * a1[q+1]
                    + u * a0[q] + cKF * a0[q+1] - u * a0[q+2] + u * a0[q+3]
                    + KF1 * b1[q+1] + KF2 * b2[q+1] + KF3 * b3[q+1];
                acc[1][q] -=
                      KB0 * a4[q] + KB1 * a3[q] + KB2 * a2[q+2]
                    - u * a1[q] + c01 * a1[q+1] + cKB * a1[q+2] - u * a1[q+3]
                    + c11 * a0[q+1]
                    + u * b1[q] + cKF * b1[q+1] - u * b1[q+2] + u * b1[q+3]
                    + KF1 * b2[q+1] + KF2 * b3[q+1] + KF3 * b4[q+1];
            }
        }

        // ---- epilogue ----
#pragma unroll
        for (int rr = 0; rr < 2; rr++) {
            const int i = r + rr;
            float2 ep = *reinterpret_cast<const float2*>(ein + (size_t)i * PE + j0);
            const float o0 = ep.x + CFLc * acc[rr][0];
            const float o1 = ep.y + CFLc * acc[rr][1];
            eo[(size_t)i * ES + j0]     = o0;
            eo[(size_t)i * ES + j0 + 1] = o1;
            *reinterpret_cast<float2*>(epo + (size_t)i * PE + j0) = make_float2(o0, o1);
        }
        return;
    }

    // ---- generic path (edges) ----
#define HXg(rr,cc) hx[(rr) * HXS + (cc)]
#define HYg(rr,cc) hyp[(rr) * PHY + (cc)]
    for (int rr = 0; rr < 2; rr++) {
        const int i = r + rr;
        if (i > NN) break;
#pragma unroll
        for (int q = 0; q < 2; q++) {
            const int j = j0 + q;
            if (j > NN) break;

            const bool iin = (i >= 2) && (i <= NN - 2);
            const bool jin = (j >= 2) && (j <= NN - 2);

            float s1 = 0.0f;
            if (iin && jin) {
                s1 += -u  * HYg(i-2, j-2) + u   * HYg(i-2, j)
                    + c01 * HYg(i-1, j-2) + c11 * HYg(i-1, j-1) + c21 * HYg(i-1, j)
                    + u   * HYg(i  , j-2) - u   * HYg(i  , j)
                    - u   * HYg(i+1, j-2) + u   * HYg(i+1, j);
            }
            if (i >= 1 && j <= NN - 5)
                s1 += KF0*HYg(i-1, j) + KF1*HYg(i-1, j+1) + KF2*HYg(i-1, j+2) + KF3*HYg(i-1, j+3);
            if (i <= NN - 1 && j >= 5)
                s1 += KB0*HYg(i, j-5) + KB1*HYg(i, j-4) + KB2*HYg(i, j-3) + KB3*HYg(i, j-2);
            if (iin && (j == 1 || j == 2))
                s1 += -HYg(i-1, j-1) + 3.0f*HYg(i-1, j) - 3.0f*HYg(i-1, j+1) + HYg(i-1, j+2);
            if (iin && (j == NN-2 || j == NN-1))
                s1 += HYg(i, j-4) - 3.0f*HYg(i, j-3) + 3.0f*HYg(i, j-2) - HYg(i, j-1);

            float s2 = 0.0f;
            if (iin && jin) {
                s2 += -u  * HXg(i-2, j-2) + c01 * HXg(i-2, j-1) + u * HXg(i-2, j) - u * HXg(i-2, j+1)
                    + c11 * HXg(i-1, j-1)
                    + u   * HXg(i  , j-2) + c21 * HXg(i  , j-1) - u * HXg(i  , j) + u * HXg(i  , j+1);
            }
            if (i <= NN - 5 && j >= 1)
                s2 += KF0*HXg(i, j-1) + KF1*HXg(i+1, j-1) + KF2*HXg(i+2, j-1) + KF3*HXg(i+3, j-1);
            if (i >= 5 && j <= NN - 1)
                s2 += KB0*HXg(i-5, j) + KB1*HXg(i-4, j) + KB2*HXg(i-3, j) + KB3*HXg(i-2, j);
            if ((i == 1 || i == 2) && jin)
                s2 += -HXg(i-1, j-1) + 3.0f*HXg(i, j-1) - 3.0f*HXg(i+1, j-1) + HXg(i+2, j-1);
            if ((i == NN-2 || i == NN-1) && jin)
                s2 += HXg(i-4, j) - 3.0f*HXg(i-3, j) + 3.0f*HXg(i-2, j) - HXg(i-1, j);

            const float val = ein[(size_t)i * PE + j] + CFLc * (s1 - s2);
            eo[(size_t)i * ES + j] = val;
            epo[(size_t)i * PE + j] = val;
        }
    }
#undef HXg
#undef HYg
}

// ---------------------------------------------------------------------------
// Faraday: Hx_out = Hx - CFL*s3 ; Hy_out = Hy + CFL*s4
// Block (64,4): thread = col pair j0, rows i = R0+2ty, i+1.
// ---------------------------------------------------------------------------
__global__ __launch_bounds__(256, 4) void faraday_kernel(
    const float* __restrict__ epad_in, const float* __restrict__ Hx,
    const float* __restrict__ hyp_in,
    float* __restrict__ hxo_d, float* __restrict__ hyo_d,
    float* __restrict__ hyp_out)
{
    const int jb = blockIdx.x * 128;
    const int R0 = blockIdx.y * 8;
    const int tx = threadIdx.x;
    const int i0 = R0 + threadIdx.y * 2;
    const int j0 = jb + 2 * tx;
    const int b  = blockIdx.z;

    const float* __restrict__ ein = epad_in + (size_t)b * ES * PE;
    const float* __restrict__ hx  = Hx      + (size_t)b * HXSZ;
    const float* __restrict__ hyp = hyp_in  + (size_t)b * NN * PHY;
    float* __restrict__ hxo = hxo_d   + (size_t)b * HXSZ;
    float* __restrict__ hyo = hyo_d   + (size_t)b * HYSZ;
    float* __restrict__ hpo = hyp_out + (size_t)b * NN * PHY;

    const float u  = g_coef[0];
    const float dl = g_coef[1];
    const float c01 = u + dl - 0.5f;
    const float c11 = -2.0f * dl;
    const float c21 = dl + 0.5f - u;

    const bool fast = (R0 >= 8) && (R0 + 7 <= NN - 4) &&
                      (jb >= 128) && (jb + 127 <= NN - 4);

    if (fast) {
        float fm1[4], f0[8], f1[8], f2[6], f3[6], f4[2];
        LDROW(fm1, ein, (i0-1) * PE + j0,     2);
        LDROW(f0 , ein, (i0  ) * PE + (j0-2), 4);
        LDROW(f1 , ein, (i0+1) * PE + (j0-2), 4);
        LDROW(f2 , ein, (i0+2) * PE + (j0-2), 3);
        LDROW(f3 , ein, (i0+3) * PE + (j0-2), 3);
        LDROW(f4 , ein, (i0+4) * PE + j0,     1);

        float s3v[2][2], s4v[2][2];
#pragma unroll
        for (int q = 0; q < 2; q++) {
            s3v[0][q] = 0.5f * fm1[q+1]
                      - u * f0[q+1] + c01 * f0[q+2] + (u - 2.0f) * f0[q+3] - u * f0[q+4]
                      + (c11 - 1.5f) * f1[q+2] + 1.5f * f1[q+3]
                      + u * f2[q+1] + (c21 + 2.0f) * f2[q+2] - u * f2[q+3] + u * f2[q+4]
                      - 0.5f * f3[q+2];
            s4v[0][q] = -u * fm1[q] + u * fm1[q+2]
                      + c01 * f0[q+2] + (c11 - 1.5f) * f0[q+3]
                      + (c21 + 2.0f) * f0[q+4] - 0.5f * f0[q+5]
                      + 0.5f * f1[q+1] + (u - 2.0f) * f1[q+2] + 1.5f * f1[q+3] - u * f1[q+4]
                      - u * f2[q+2] + u * f2[q+4];
            s3v[1][q] = 0.5f * f0[q+3]
                      - u * f1[q+1] + c01 * f1[q+2] + (u - 2.0f) * f1[q+3] - u * f1[q+4]
                      + (c11 - 1.5f) * f2[q+2] + 1.5f * f2[q+3]
                      + u * f3[q+1] + (c21 + 2.0f) * f3[q+2] - u * f3[q+3] + u * f3[q+4]
                      - 0.5f * f4[q];
            s4v[1][q] = -u * f0[q+2] + u * f0[q+4]
                      + c01 * f1[q+2] + (c11 - 1.5f) * f1[q+3]
                      + (c21 + 2.0f) * f1[q+4] - 0.5f * f1[q+5]
                      + 0.5f * f2[q+1] + (u - 2.0f) * f2[q+2] + 1.5f * f2[q+3] - u * f2[q+4]
                      - u * f3[q+2] + u * f3[q+4];
        }

#pragma unroll
        for (int rr = 0; rr < 2; rr++) {
            const int i = i0 + rr;
            float2 hxp = *reinterpret_cast<const float2*>(hx  + (size_t)i * HXS + j0);
            float2 hyv = *reinterpret_cast<const float2*>(hyp + (size_t)i * PHY + j0);
            const float x0 = hxp.x - CFLc * s3v[rr][0];
            const float x1 = hxp.y - CFLc * s3v[rr][1];
            const float y0 = hyv.x + CFLc * s4v[rr][0];
            const float y1 = hyv.y + CFLc * s4v[rr][1];
            *reinterpret_cast<float2*>(hxo + (size_t)i * HXS + j0) = make_float2(x0, x1);
            hyo[(size_t)i * HYS + j0]     = y0;
            hyo[(size_t)i * HYS + j0 + 1] = y1;
            *reinterpret_cast<float2*>(hpo + (size_t)i * PHY + j0) = make_float2(y0, y1);
        }
        return;
    }

    // ---- generic path (edges) ----
#define EEg(rr,cc) ein[(rr) * PE + (cc)]
    for (int rr = 0; rr < 2; rr++) {
        const int i = i0 + rr;
        if (i >= NN) break;
#pragma unroll
        for (int q = 0; q < 2; q++) {
            const int j = j0 + q;
            if (j >= NN) break;

            if (i <= NN - 2) {
                float s3 = 0.0f;
                if (j >= 1 && j <= NN - 2) {
                    s3 += -u  * EEg(i  , j-1) + c01 * EEg(i  , j) + u * EEg(i  , j+1) - u * EEg(i  , j+2)
                        + c11 * EEg(i+1, j)
                        + u   * EEg(i+2, j-1) + c21 * EEg(i+2, j) - u * EEg(i+2, j+1) + u * EEg(i+2, j+2);
                }
                if (i <= NN - 4)
                    s3 += -1.5f * EEg(i+1, j) + 2.0f * EEg(i+2, j) - 0.5f * EEg(i+3, j);
                if (i >= 2)
                    s3 +=  0.5f * EEg(i-1, j+1) - 2.0f * EEg(i, j+1) + 1.5f * EEg(i+1, j+1);
                hxo[(size_t)i * HXS + j] = hx[(size_t)i * HXS + j] - CFLc * s3;
            }

            if (j <= NN - 2) {
                float s4 = 0.0f;
                if (i >= 1 && i <= NN - 2) {
                    s4 += -u  * EEg(i-1, j) + u * EEg(i-1, j+2)
                        + c01 * EEg(i  , j) + c11 * EEg(i, j+1) + c21 * EEg(i, j+2)
                        + u   * EEg(i+1, j) - u * EEg(i+1, j+2)
                        - u   * EEg(i+2, j) + u * EEg(i+2, j+2);
                }
                if (j <= NN - 4)
                    s4 += -1.5f * EEg(i, j+1) + 2.0f * EEg(i, j+2) - 0.5f * EEg(i, j+3);
                if (j >= 2)
                    s4 +=  0.5f * EEg(i+1, j-1) - 2.0f * EEg(i+1, j) + 1.5f * EEg(i+1, j+1);
                const float val = hyp[(size_t)i * PHY + j] + CFLc * s4;
                hyo[(size_t)i * HYS + j] = val;
                hpo[(size_t)i * PHY + j] = val;
            }
        }
    }
#undef EEg
}

// ---------------------------------------------------------------------------
extern "C" void kernel_launch(void* const* d_in, const int* in_sizes, int n_in,
                              void* d_out, int out_size)
{
    const float* E0    = (const float*)d_in[0];
    const float* Hx0   = (const float*)d_in[1];
    const float* Hy0   = (const float*)d_in[2];
    const float* beta  = (const float*)d_in[3];
    const float* delta = (const float*)d_in[4];
    const float* gamma = (const float*)d_in[5];

    float* out = (float*)d_out;
    const size_t esz  = (size_t)BB * ESZ;
    const size_t hxsz = (size_t)BB * HXSZ;
    const size_t hysz = (size_t)BB * HYSZ;

    float* E2  = out;
    float* Hx2 = E2  + esz;
    float* Hy2 = Hx2 + hxsz;
    float* E3  = Hy2 + hysz;
    float* Hx3 = E3  + esz;
    float* Hy3 = Hx3 + hxsz;
    float* E4  = Hy3 + hysz;
    float* Hx4 = E4  + esz;
    float* Hy4 = Hx4 + hxsz;

    float *EA, *EB, *HA, *HB;
    cudaGetSymbolAddress((void**)&EA, g_EpadA);
    cudaGetSymbolAddress((void**)&EB, g_EpadB);
    cudaGetSymbolAddress((void**)&HA, g_HyA);
    cudaGetSymbolAddress((void**)&HB, g_HyB);

    coef_kernel<<<1, 1>>>(beta, delta, gamma);

    const int eTot  = BB * ES * ES;
    const int hyTot = BB * NN * HYS;
    repackE_kernel <<<(eTot  + 255) / 256, 256>>>(E0);
    repackHy_kernel<<<(hyTot + 255) / 256, 256>>>(Hy0);

    dim3 blk(64, 4, 1);
    dim3 gE(17, (ES + 7) / 8, BB);   // 17 x 257 x 2
    dim3 gF(16, NN / 8, BB);         // 16 x 256 x 2

    // step 1
    amper_kernel  <<<gE, blk>>>(EA, Hx0, HA, E2, EB);
    faraday_kernel<<<gF, blk>>>(EB, Hx0, HA, Hx2, Hy2, HB);
    // step 2
    amper_kernel  <<<gE, blk>>>(EB, Hx2, HB, E3, EA);
    faraday_kernel<<<gF, blk>>>(EA, Hx2, HB, Hx3, Hy3, HA);
    // step 3
    amper_kernel  <<<gE, blk>>>(EA, Hx3, HA, E4, EB);
    faraday_kernel<<<gF, blk>>>(EB, Hx3, HA, Hx4, Hy4, HB);
}

// round 11
// speedup vs baseline: 1.3264x; 1.0407x over previous
#include <cuda_runtime.h>

// DRP_LAYER: 2D DRP-FDTD, 3 steps, B=2, N=2048.
// R11: R10 with the misaligned E d_out f2 store reverted to scalar
// (ESZ is odd -> batch-1 E slice base is odd; only Hy f2 store is safe).
// Keeps __launch_bounds__(256,5) occupancy experiment.

#define NN   2048
#define BB   2
#define CFLc 0.35f

#define ES   (NN + 1)
#define HXS  (NN)
#define HYS  (NN - 1)
#define ESZ  ((NN + 1) * (NN + 1))
#define HXSZ ((NN - 1) * NN)
#define HYSZ (NN * (NN - 1))

#define PE   2052
#define PHY  2048

__device__ __align__(16) float g_EpadA[BB * (NN + 1) * PE];
__device__ __align__(16) float g_EpadB[BB * (NN + 1) * PE];
__device__ __align__(16) float g_HyA[BB * NN * PHY];
__device__ __align__(16) float g_HyB[BB * NN * PHY];

__device__ float g_coef[2];

__global__ void coef_kernel(const float* __restrict__ beta,
                            const float* __restrict__ delta,
                            const float* __restrict__ gamma) {
    g_coef[0] = 0.25f * beta[0] - 0.1f * gamma[0];
    g_coef[1] = delta[0];
}

__global__ void repackE_kernel(const float* __restrict__ E0) {
    int idx = blockIdx.x * blockDim.x + threadIdx.x;
    const int tot = BB * ES * ES;
    if (idx >= tot) return;
    int b = idx / (ES * ES);
    int r = (idx / ES) % ES;
    int c = idx % ES;
    g_EpadA[((size_t)b * ES + r) * PE + c] = E0[idx];
}

__global__ void repackHy_kernel(const float* __restrict__ Hy0) {
    int idx = blockIdx.x * blockDim.x + threadIdx.x;
    const int tot = BB * NN * HYS;
    if (idx >= tot) return;
    int b = idx / (NN * HYS);
    int r = (idx / HYS) % NN;
    int c = idx % HYS;
    g_HyA[((size_t)b * NN + r) * PHY + c] = Hy0[idx];
}

#define KF0 (-11.0f/6.0f)
#define KF1 (3.0f)
#define KF2 (-1.5f)
#define KF3 (1.0f/3.0f)
#define KB0 (-1.0f/3.0f)
#define KB1 (1.5f)
#define KB2 (-3.0f)
#define KB3 (11.0f/6.0f)

#define LDROW(dst, base, off, n) do {                                      \
    const float2* _p = reinterpret_cast<const float2*>((base) + (off));    \
    _Pragma("unroll")                                                      \
    for (int _k = 0; _k < (n); _k++) {                                     \
        float2 _v = _p[_k]; (dst)[2*_k] = _v.x; (dst)[2*_k+1] = _v.y;      \
    } } while (0)

// ---------------------------------------------------------------------------
// Ampere: E_out = E + CFL*(s1 - s2).
// Block (64,4): thread = col pair j0 = jb+2tx, rows r = R0+2ty, r+1.
// ---------------------------------------------------------------------------
__global__ __launch_bounds__(256, 5) void amper_kernel(
    const float* __restrict__ epad_in, const float* __restrict__ Hx,
    const float* __restrict__ hyp_in,
    float* __restrict__ eo_d, float* __restrict__ epad_out)
{
    const int jb = blockIdx.x * 128;
    const int R0 = blockIdx.y * 8;
    const int tx = threadIdx.x;
    const int r  = R0 + threadIdx.y * 2;
    const int j0 = jb + 2 * tx;
    const int b  = blockIdx.z;

    const float* __restrict__ ein = epad_in + (size_t)b * ES * PE;
    const float* __restrict__ hx  = Hx      + (size_t)b * HXSZ;
    const float* __restrict__ hyp = hyp_in  + (size_t)b * NN * PHY;
    float* __restrict__ eo  = eo_d     + (size_t)b * ESZ;
    float* __restrict__ epo = epad_out + (size_t)b * ES * PE;

    const float u  = g_coef[0];
    const float dl = g_coef[1];
    const float c01 = u + dl - 0.5f;
    const float c11 = -2.0f * dl;
    const float c21 = dl + 0.5f - u;
    const float cKF = c21 + KF0;
    const float cKB = u + KB3;

    const bool fast = (R0 >= 8) && (R0 + 7 <= NN - 5) &&
                      (jb >= 128) && (jb + 127 <= NN - 5);

    if (fast) {
        float acc[2][2];

        // ---- Hy rows r-2..r+2, merged spans ----
        {
            float hm2[4], hm1[8], h0[12], hp1[8], hp2[4];
            LDROW(hm2, hyp, (r-2) * PHY + (j0-2), 2);
            LDROW(hm1, hyp, (r-1) * PHY + (j0-2), 4);
            LDROW(h0 , hyp, (r  ) * PHY + (j0-6), 6);
            LDROW(hp1, hyp, (r+1) * PHY + (j0-6), 4);
            LDROW(hp2, hyp, (r+2) * PHY + (j0-2), 2);
#pragma unroll
            for (int q = 0; q < 2; q++) {
                acc[0][q] =
                      -u * hm2[q] + u * hm2[q+2]
                    + c01 * hm1[q] + c11 * hm1[q+1] + cKF * hm1[q+2]
                    + KF1 * hm1[q+3] + KF2 * hm1[q+4] + KF3 * hm1[q+5]
                    + KB0 * h0[q+1] + KB1 * h0[q+2] + KB2 * h0[q+3]
                    + cKB * h0[q+4] - u * h0[q+6]
                    - u * hp1[q+4] + u * hp1[q+6];
                acc[1][q] =
                      -u * hm1[q] + u * hm1[q+2]
                    + c01 * h0[q+4] + c11 * h0[q+5] + cKF * h0[q+6]
                    + KF1 * h0[q+7] + KF2 * h0[q+8] + KF3 * h0[q+9]
                    + KB0 * hp1[q+1] + KB1 * hp1[q+2] + KB2 * hp1[q+3]
                    + cKB * hp1[q+4] - u * hp1[q+6]
                    - u * hp2[q] + u * hp2[q+2];
            }
        }

        // ---- Hx rows r-5..r+4, merged spans ----
        {
            float a5[2], a4[2], a3[2], a2[6], a1[6], a0[6], b1[6], b2[4], b3[4], b4[4];
            LDROW(a5, hx, (r-5) * HXS + j0,     1);
            LDROW(a4, hx, (r-4) * HXS + j0,     1);
            LDROW(a3, hx, (r-3) * HXS + j0,     1);
            LDROW(a2, hx, (r-2) * HXS + (j0-2), 3);
            LDROW(a1, hx, (r-1) * HXS + (j0-2), 3);
            LDROW(a0, hx, (r  ) * HXS + (j0-2), 3);
            LDROW(b1, hx, (r+1) * HXS + (j0-2), 3);
            LDROW(b2, hx, (r+2) * HXS + (j0-2), 2);
            LDROW(b3, hx, (r+3) * HXS + (j0-2), 2);
            LDROW(b4, hx, (r+4) * HXS + (j0-2), 2);
#pragma unroll
            for (int q = 0; q < 2; q++) {
                acc[0][q] -=
                      KB0 * a5[q] + KB1 * a4[q] + KB2 * a3[q]
                    - u * a2[q] + c01 * a2[q+1] + cKB * a2[q+2] - u * a2[q+3]
                    + c11 * a1[q+1]
                    + u * a0[q] + cKF * a0[q+1] - u * a0[q+2] + u * a0[q+3]
                    + KF1 * b1[q+1] + KF2 * b2[q+1] + KF3 * b3[q+1];
                acc[1][q] -=
                      KB0 * a4[q] + KB1 * a3[q] + KB2 * a2[q+2]
                    - u * a1[q] + c01 * a1[q+1] + cKB * a1[q+2] - u * a1[q+3]
                    + c11 * a0[q+1]
                    + u * b1[q] + cKF * b1[q+1] - u * b1[q+2] + u * b1[q+3]
                    + KF1 * b2[q+1] + KF2 * b3[q+1] + KF3 * b4[q+1];
            }
        }

        // ---- epilogue (E d_out: scalar stores — slice base parity varies) ----
#pragma unroll
        for (int rr = 0; rr < 2; rr++) {
            const int i = r + rr;
            float2 ep = *reinterpret_cast<const float2*>(ein + (size_t)i * PE + j0);
            const float o0 = ep.x + CFLc * acc[rr][0];
            const float o1 = ep.y + CFLc * acc[rr][1];
            eo[(size_t)i * ES + j0]     = o0;
            eo[(size_t)i * ES + j0 + 1] = o1;
            *reinterpret_cast<float2*>(epo + (size_t)i * PE + j0) = make_float2(o0, o1);
        }
        return;
    }

    // ---- generic path (edges) ----
#define HXg(rr,cc) hx[(rr) * HXS + (cc)]
#define HYg(rr,cc) hyp[(rr) * PHY + (cc)]
    for (int rr = 0; rr < 2; rr++) {
        const int i = r + rr;
        if (i > NN) break;
#pragma unroll
        for (int q = 0; q < 2; q++) {
            const int j = j0 + q;
            if (j > NN) break;

            const bool iin = (i >= 2) && (i <= NN - 2);
            const bool jin = (j >= 2) && (j <= NN - 2);

            float s1 = 0.0f;
            if (iin && jin) {
                s1 += -u  * HYg(i-2, j-2) + u   * HYg(i-2, j)
                    + c01 * HYg(i-1, j-2) + c11 * HYg(i-1, j-1) + c21 * HYg(i-1, j)
                    + u   * HYg(i  , j-2) - u   * HYg(i  , j)
                    - u   * HYg(i+1, j-2) + u   * HYg(i+1, j);
            }
            if (i >= 1 && j <= NN - 5)
                s1 += KF0*HYg(i-1, j) + KF1*HYg(i-1, j+1) + KF2*HYg(i-1, j+2) + KF3*HYg(i-1, j+3);
            if (i <= NN - 1 && j >= 5)
                s1 += KB0*HYg(i, j-5) + KB1*HYg(i, j-4) + KB2*HYg(i, j-3) + KB3*HYg(i, j-2);
            if (iin && (j == 1 || j == 2))
                s1 += -HYg(i-1, j-1) + 3.0f*HYg(i-1, j) - 3.0f*HYg(i-1, j+1) + HYg(i-1, j+2);
            if (iin && (j == NN-2 || j == NN-1))
                s1 += HYg(i, j-4) - 3.0f*HYg(i, j-3) + 3.0f*HYg(i, j-2) - HYg(i, j-1);

            float s2 = 0.0f;
            if (iin && jin) {
                s2 += -u  * HXg(i-2, j-2) + c01 * HXg(i-2, j-1) + u * HXg(i-2, j) - u * HXg(i-2, j+1)
                    + c11 * HXg(i-1, j-1)
                    + u   * HXg(i  , j-2) + c21 * HXg(i  , j-1) - u * HXg(i  , j) + u * HXg(i  , j+1);
            }
            if (i <= NN - 5 && j >= 1)
                s2 += KF0*HXg(i, j-1) + KF1*HXg(i+1, j-1) + KF2*HXg(i+2, j-1) + KF3*HXg(i+3, j-1);
            if (i >= 5 && j <= NN - 1)
                s2 += KB0*HXg(i-5, j) + KB1*HXg(i-4, j) + KB2*HXg(i-3, j) + KB3*HXg(i-2, j);
            if ((i == 1 || i == 2) && jin)
                s2 += -HXg(i-1, j-1) + 3.0f*HXg(i, j-1) - 3.0f*HXg(i+1, j-1) + HXg(i+2, j-1);
            if ((i == NN-2 || i == NN-1) && jin)
                s2 += HXg(i-4, j) - 3.0f*HXg(i-3, j) + 3.0f*HXg(i-2, j) - HXg(i-1, j);

            const float val = ein[(size_t)i * PE + j] + CFLc * (s1 - s2);
            eo[(size_t)i * ES + j] = val;
            epo[(size_t)i * PE + j] = val;
        }
    }
#undef HXg
#undef HYg
}

// ---------------------------------------------------------------------------
// Faraday: Hx_out = Hx - CFL*s3 ; Hy_out = Hy + CFL*s4
// Block (64,4): thread = col pair j0, rows i = R0+2ty (even), i+1.
// Hy d_out slice bases and HYSZ are even -> even-row f2 store is aligned.
// ---------------------------------------------------------------------------
__global__ __launch_bounds__(256, 5) void faraday_kernel(
    const float* __restrict__ epad_in, const float* __restrict__ Hx,
    const float* __restrict__ hyp_in,
    float* __restrict__ hxo_d, float* __restrict__ hyo_d,
    float* __restrict__ hyp_out)
{
    const int jb = blockIdx.x * 128;
    const int R0 = blockIdx.y * 8;
    const int tx = threadIdx.x;
    const int i0 = R0 + threadIdx.y * 2;
    const int j0 = jb + 2 * tx;
    const int b  = blockIdx.z;

    const float* __restrict__ ein = epad_in + (size_t)b * ES * PE;
    const float* __restrict__ hx  = Hx      + (size_t)b * HXSZ;
    const float* __restrict__ hyp = hyp_in  + (size_t)b * NN * PHY;
    float* __restrict__ hxo = hxo_d   + (size_t)b * HXSZ;
    float* __restrict__ hyo = hyo_d   + (size_t)b * HYSZ;
    float* __restrict__ hpo = hyp_out + (size_t)b * NN * PHY;

    const float u  = g_coef[0];
    const float dl = g_coef[1];
    const float c01 = u + dl - 0.5f;
    const float c11 = -2.0f * dl;
    const float c21 = dl + 0.5f - u;

    const bool fast = (R0 >= 8) && (R0 + 7 <= NN - 4) &&
                      (jb >= 128) && (jb + 127 <= NN - 4);

    if (fast) {
        float fm1[4], f0[8], f1[8], f2[6], f3[6], f4[2];
        LDROW(fm1, ein, (i0-1) * PE + j0,     2);
        LDROW(f0 , ein, (i0  ) * PE + (j0-2), 4);
        LDROW(f1 , ein, (i0+1) * PE + (j0-2), 4);
        LDROW(f2 , ein, (i0+2) * PE + (j0-2), 3);
        LDROW(f3 , ein, (i0+3) * PE + (j0-2), 3);
        LDROW(f4 , ein, (i0+4) * PE + j0,     1);

        float s3v[2][2], s4v[2][2];
#pragma unroll
        for (int q = 0; q < 2; q++) {
            s3v[0][q] = 0.5f * fm1[q+1]
                      - u * f0[q+1] + c01 * f0[q+2] + (u - 2.0f) * f0[q+3] - u * f0[q+4]
                      + (c11 - 1.5f) * f1[q+2] + 1.5f * f1[q+3]
                      + u * f2[q+1] + (c21 + 2.0f) * f2[q+2] - u * f2[q+3] + u * f2[q+4]
                      - 0.5f * f3[q+2];
            s4v[0][q] = -u * fm1[q] + u * fm1[q+2]
                      + c01 * f0[q+2] + (c11 - 1.5f) * f0[q+3]
                      + (c21 + 2.0f) * f0[q+4] - 0.5f * f0[q+5]
                      + 0.5f * f1[q+1] + (u - 2.0f) * f1[q+2] + 1.5f * f1[q+3] - u * f1[q+4]
                      - u * f2[q+2] + u * f2[q+4];
            s3v[1][q] = 0.5f * f0[q+3]
                      - u * f1[q+1] + c01 * f1[q+2] + (u - 2.0f) * f1[q+3] - u * f1[q+4]
                      + (c11 - 1.5f) * f2[q+2] + 1.5f * f2[q+3]
                      + u * f3[q+1] + (c21 + 2.0f) * f3[q+2] - u * f3[q+3] + u * f3[q+4]
                      - 0.5f * f4[q];
            s4v[1][q] = -u * f0[q+2] + u * f0[q+4]
                      + c01 * f1[q+2] + (c11 - 1.5f) * f1[q+3]
                      + (c21 + 2.0f) * f1[q+4] - 0.5f * f1[q+5]
                      + 0.5f * f2[q+1] + (u - 2.0f) * f2[q+2] + 1.5f * f2[q+3] - u * f2[q+4]
                      - u * f3[q+2] + u * f3[q+4];
        }

        // row i0 (even): hyo offset even and slice base even -> f2 store
        {
            float2 hxp = *reinterpret_cast<const float2*>(hx  + (size_t)i0 * HXS + j0);
            float2 hyv = *reinterpret_cast<const float2*>(hyp + (size_t)i0 * PHY + j0);
            const float x0 = hxp.x - CFLc * s3v[0][0];
            const float x1 = hxp.y - CFLc * s3v[0][1];
            const float y0 = hyv.x + CFLc * s4v[0][0];
            const float y1 = hyv.y + CFLc * s4v[0][1];
            *reinterpret_cast<float2*>(hxo + (size_t)i0 * HXS + j0) = make_float2(x0, x1);
            *reinterpret_cast<float2*>(hyo + (size_t)i0 * HYS + j0) = make_float2(y0, y1);
            *reinterpret_cast<float2*>(hpo + (size_t)i0 * PHY + j0) = make_float2(y0, y1);
        }
        {
            const int i = i0 + 1;
            float2 hxp = *reinterpret_cast<const float2*>(hx  + (size_t)i * HXS + j0);
            float2 hyv = *reinterpret_cast<const float2*>(hyp + (size_t)i * PHY + j0);
            const float x0 = hxp.x - CFLc * s3v[1][0];
            const float x1 = hxp.y - CFLc * s3v[1][1];
            const float y0 = hyv.x + CFLc * s4v[1][0];
            const float y1 = hyv.y + CFLc * s4v[1][1];
            *reinterpret_cast<float2*>(hxo + (size_t)i * HXS + j0) = make_float2(x0, x1);
            hyo[(size_t)i * HYS + j0]     = y0;
            hyo[(size_t)i * HYS + j0 + 1] = y1;
            *reinterpret_cast<float2*>(hpo + (size_t)i * PHY + j0) = make_float2(y0, y1);
        }
        return;
    }

    // ---- generic path (edges) ----
#define EEg(rr,cc) ein[(rr) * PE + (cc)]
    for (int rr = 0; rr < 2; rr++) {
        const int i = i0 + rr;
        if (i >= NN) break;
#pragma unroll
        for (int q = 0; q < 2; q++) {
            const int j = j0 + q;
            if (j >= NN) break;

            if (i <= NN - 2) {
                float s3 = 0.0f;
                if (j >= 1 && j <= NN - 2) {
                    s3 += -u  * EEg(i  , j-1) + c01 * EEg(i  , j) + u * EEg(i  , j+1) - u * EEg(i  , j+2)
                        + c11 * EEg(i+1, j)
                        + u   * EEg(i+2, j-1) + c21 * EEg(i+2, j) - u * EEg(i+2, j+1) + u * EEg(i+2, j+2);
                }
                if (i <= NN - 4)
                    s3 += -1.5f * EEg(i+1, j) + 2.0f * EEg(i+2, j) - 0.5f * EEg(i+3, j);
                if (i >= 2)
                    s3 +=  0.5f * EEg(i-1, j+1) - 2.0f * EEg(i, j+1) + 1.5f * EEg(i+1, j+1);
                hxo[(size_t)i * HXS + j] = hx[(size_t)i * HXS + j] - CFLc * s3;
            }

            if (j <= NN - 2) {
                float s4 = 0.0f;
                if (i >= 1 && i <= NN - 2) {
                    s4 += -u  * EEg(i-1, j) + u * EEg(i-1, j+2)
                        + c01 * EEg(i  , j) + c11 * EEg(i, j+1) + c21 * EEg(i, j+2)
                        + u   * EEg(i+1, j) - u * EEg(i+1, j+2)
                        - u   * EEg(i+2, j) + u * EEg(i+2, j+2);
                }
                if (j <= NN - 4)
                    s4 += -1.5f * EEg(i, j+1) + 2.0f * EEg(i, j+2) - 0.5f * EEg(i, j+3);
                if (j >= 2)
                    s4 +=  0.5f * EEg(i+1, j-1) - 2.0f * EEg(i+1, j) + 1.5f * EEg(i+1, j+1);
                const float val = hyp[(size_t)i * PHY + j] + CFLc * s4;
                hyo[(size_t)i * HYS + j] = val;
                hpo[(size_t)i * PHY + j] = val;
            }
        }
    }
#undef EEg
}

// ---------------------------------------------------------------------------
extern "C" void kernel_launch(void* const* d_in, const int* in_sizes, int n_in,
                              void* d_out, int out_size)
{
    const float* E0    = (const float*)d_in[0];
    const float* Hx0   = (const float*)d_in[1];
    const float* Hy0   = (const float*)d_in[2];
    const float* beta  = (const float*)d_in[3];
    const float* delta = (const float*)d_in[4];
    const float* gamma = (const float*)d_in[5];

    float* out = (float*)d_out;
    const size_t esz  = (size_t)BB * ESZ;
    const size_t hxsz = (size_t)BB * HXSZ;
    const size_t hysz = (size_t)BB * HYSZ;

    float* E2  = out;
    float* Hx2 = E2  + esz;
    float* Hy2 = Hx2 + hxsz;
    float* E3  = Hy2 + hysz;
    float* Hx3 = E3  + esz;
    float* Hy3 = Hx3 + hxsz;
    float* E4  = Hy3 + hysz;
    float* Hx4 = E4  + esz;
    float* Hy4 = Hx4 + hxsz;

    float *EA, *EB, *HA, *HB;
    cudaGetSymbolAddress((void**)&EA, g_EpadA);
    cudaGetSymbolAddress((void**)&EB, g_EpadB);
    cudaGetSymbolAddress((void**)&HA, g_HyA);
    cudaGetSymbolAddress((void**)&HB, g_HyB);

    coef_kernel<<<1, 1>>>(beta, delta, gamma);

    const int eTot  = BB * ES * ES;
    const int hyTot = BB * NN * HYS;
    repackE_kernel <<<(eTot  + 255) / 256, 256>>>(E0);
    repackHy_kernel<<<(hyTot + 255) / 256, 256>>>(Hy0);

    dim3 blk(64, 4, 1);
    dim3 gE(17, (ES + 7) / 8, BB);   // 17 x 257 x 2
    dim3 gF(16, NN / 8, BB);         // 16 x 256 x 2

    // step 1
    amper_kernel  <<<gE, blk>>>(EA, Hx0, HA, E2, EB);
    faraday_kernel<<<gF, blk>>>(EB, Hx0, HA, Hx2, Hy2, HB);
    // step 2
    amper_kernel  <<<gE, blk>>>(EB, Hx2, HB, E3, EA);
    faraday_kernel<<<gF, blk>>>(EA, Hx2, HB, Hx3, Hy3, HA);
    // step 3
    amper_kernel  <<<gE, blk>>>(EA, Hx3, HA, E4, EB);
    faraday_kernel<<<gF, blk>>>(EB, Hx3, HA, Hx4, Hy4, HB);
}

// round 12
// speedup vs baseline: 1.5491x; 1.1679x over previous
#include <cuda_runtime.h>

// DRP_LAYER: 2D DRP-FDTD, 3 steps, B=2, N=2048.
// R12: R11 + repack elimination. Step-1 kernels are templated to read the
// raw (odd-stride) inputs directly with scalar coalesced loads; steps 2-3
// keep float2 loads on even-stride padded ping-pong buffers.

#define NN   2048
#define BB   2
#define CFLc 0.35f

#define ES   (NN + 1)
#define HXS  (NN)
#define HYS  (NN - 1)
#define ESZ  ((NN + 1) * (NN + 1))
#define HXSZ ((NN - 1) * NN)
#define HYSZ (NN * (NN - 1))

#define PE   2052
#define PHY  2048

__device__ __align__(16) float g_EpadA[BB * (NN + 1) * PE];
__device__ __align__(16) float g_EpadB[BB * (NN + 1) * PE];
__device__ __align__(16) float g_HyA[BB * NN * PHY];
__device__ __align__(16) float g_HyB[BB * NN * PHY];

__device__ float g_coef[2];

__global__ void coef_kernel(const float* __restrict__ beta,
                            const float* __restrict__ delta,
                            const float* __restrict__ gamma) {
    g_coef[0] = 0.25f * beta[0] - 0.1f * gamma[0];
    g_coef[1] = delta[0];
}

#define KF0 (-11.0f/6.0f)
#define KF1 (3.0f)
#define KF2 (-1.5f)
#define KF3 (1.0f/3.0f)
#define KB0 (-1.0f/3.0f)
#define KB1 (1.5f)
#define KB2 (-3.0f)
#define KB3 (11.0f/6.0f)

// Load NP float2-pairs (2*NP floats). VEC=true uses aligned float2 loads.
template<int NP, bool VEC>
__device__ __forceinline__ void ldrow(float* dst, const float* p) {
    if constexpr (VEC) {
        const float2* q = reinterpret_cast<const float2*>(p);
#pragma unroll
        for (int k = 0; k < NP; k++) { float2 v = q[k]; dst[2*k] = v.x; dst[2*k+1] = v.y; }
    } else {
#pragma unroll
        for (int k = 0; k < 2 * NP; k++) dst[k] = p[k];
    }
}

// ---------------------------------------------------------------------------
// Ampere: E_out = E + CFL*(s1 - s2).
// Block (64,4): thread = col pair j0 = jb+2tx, rows r = R0+2ty, r+1.
// RAW=true: E/Hy inputs are the raw odd-stride tensors (step 1).
// ---------------------------------------------------------------------------
template<bool RAW>
__global__ __launch_bounds__(256, 5) void amper_kernel(
    const float* __restrict__ epad_in, const float* __restrict__ Hx,
    const float* __restrict__ hyp_in,
    float* __restrict__ eo_d, float* __restrict__ epad_out)
{
    constexpr int EI  = RAW ? ES  : PE;    // E input stride
    constexpr int HYI = RAW ? HYS : PHY;   // Hy input stride
    constexpr size_t EIB  = RAW ? (size_t)ESZ  : (size_t)ES * PE;
    constexpr size_t HYIB = RAW ? (size_t)HYSZ : (size_t)NN * PHY;
    constexpr bool V = !RAW;

    const int jb = blockIdx.x * 128;
    const int R0 = blockIdx.y * 8;
    const int tx = threadIdx.x;
    const int r  = R0 + threadIdx.y * 2;
    const int j0 = jb + 2 * tx;
    const int b  = blockIdx.z;

    const float* __restrict__ ein = epad_in + (size_t)b * EIB;
    const float* __restrict__ hx  = Hx      + (size_t)b * HXSZ;
    const float* __restrict__ hyp = hyp_in  + (size_t)b * HYIB;
    float* __restrict__ eo  = eo_d     + (size_t)b * ESZ;
    float* __restrict__ epo = epad_out + (size_t)b * ES * PE;

    const float u  = g_coef[0];
    const float dl = g_coef[1];
    const float c01 = u + dl - 0.5f;
    const float c11 = -2.0f * dl;
    const float c21 = dl + 0.5f - u;
    const float cKF = c21 + KF0;
    const float cKB = u + KB3;

    const bool fast = (R0 >= 8) && (R0 + 7 <= NN - 5) &&
                      (jb >= 128) && (jb + 127 <= NN - 5);

    if (fast) {
        float acc[2][2];

        // ---- Hy rows r-2..r+2, merged spans ----
        {
            float hm2[4], hm1[8], h0[12], hp1[8], hp2[4];
            ldrow<2, V>(hm2, hyp + (r-2) * HYI + (j0-2));
            ldrow<4, V>(hm1, hyp + (r-1) * HYI + (j0-2));
            ldrow<6, V>(h0 , hyp + (r  ) * HYI + (j0-6));
            ldrow<4, V>(hp1, hyp + (r+1) * HYI + (j0-6));
            ldrow<2, V>(hp2, hyp + (r+2) * HYI + (j0-2));
#pragma unroll
            for (int q = 0; q < 2; q++) {
                acc[0][q] =
                      -u * hm2[q] + u * hm2[q+2]
                    + c01 * hm1[q] + c11 * hm1[q+1] + cKF * hm1[q+2]
                    + KF1 * hm1[q+3] + KF2 * hm1[q+4] + KF3 * hm1[q+5]
                    + KB0 * h0[q+1] + KB1 * h0[q+2] + KB2 * h0[q+3]
                    + cKB * h0[q+4] - u * h0[q+6]
                    - u * hp1[q+4] + u * hp1[q+6];
                acc[1][q] =
                      -u * hm1[q] + u * hm1[q+2]
                    + c01 * h0[q+4] + c11 * h0[q+5] + cKF * h0[q+6]
                    + KF1 * h0[q+7] + KF2 * h0[q+8] + KF3 * h0[q+9]
                    + KB0 * hp1[q+1] + KB1 * hp1[q+2] + KB2 * hp1[q+3]
                    + cKB * hp1[q+4] - u * hp1[q+6]
                    - u * hp2[q] + u * hp2[q+2];
            }
        }

        // ---- Hx rows r-5..r+4, merged spans (Hx always even-stride) ----
        {
            float a5[2], a4[2], a3[2], a2[6], a1[6], a0[6], b1[6], b2[4], b3[4], b4[4];
            ldrow<1, true>(a5, hx + (r-5) * HXS + j0);
            ldrow<1, true>(a4, hx + (r-4) * HXS + j0);
            ldrow<1, true>(a3, hx + (r-3) * HXS + j0);
            ldrow<3, true>(a2, hx + (r-2) * HXS + (j0-2));
            ldrow<3, true>(a1, hx + (r-1) * HXS + (j0-2));
            ldrow<3, true>(a0, hx + (r  ) * HXS + (j0-2));
            ldrow<3, true>(b1, hx + (r+1) * HXS + (j0-2));
            ldrow<2, true>(b2, hx + (r+2) * HXS + (j0-2));
            ldrow<2, true>(b3, hx + (r+3) * HXS + (j0-2));
            ldrow<2, true>(b4, hx + (r+4) * HXS + (j0-2));
#pragma unroll
            for (int q = 0; q < 2; q++) {
                acc[0][q] -=
                      KB0 * a5[q] + KB1 * a4[q] + KB2 * a3[q]
                    - u * a2[q] + c01 * a2[q+1] + cKB * a2[q+2] - u * a2[q+3]
                    + c11 * a1[q+1]
                    + u * a0[q] + cKF * a0[q+1] - u * a0[q+2] + u * a0[q+3]
                    + KF1 * b1[q+1] + KF2 * b2[q+1] + KF3 * b3[q+1];
                acc[1][q] -=
                      KB0 * a4[q] + KB1 * a3[q] + KB2 * a2[q+2]
                    - u * a1[q] + c01 * a1[q+1] + cKB * a1[q+2] - u * a1[q+3]
                    + c11 * a0[q+1]
                    + u * b1[q] + cKF * b1[q+1] - u * b1[q+2] + u * b1[q+3]
                    + KF1 * b2[q+1] + KF2 * b3[q+1] + KF3 * b4[q+1];
            }
        }

        // ---- epilogue ----
#pragma unroll
        for (int rr = 0; rr < 2; rr++) {
            const int i = r + rr;
            float ein0, ein1;
            {
                float tmp[2];
                ldrow<1, V>(tmp, ein + (size_t)i * EI + j0);
                ein0 = tmp[0]; ein1 = tmp[1];
            }
            const float o0 = ein0 + CFLc * acc[rr][0];
            const float o1 = ein1 + CFLc * acc[rr][1];
            eo[(size_t)i * ES + j0]     = o0;
            eo[(size_t)i * ES + j0 + 1] = o1;
            *reinterpret_cast<float2*>(epo + (size_t)i * PE + j0) = make_float2(o0, o1);
        }
        return;
    }

    // ---- generic path (edges) ----
#define HXg(rr,cc) hx[(rr) * HXS + (cc)]
#define HYg(rr,cc) hyp[(rr) * HYI + (cc)]
    for (int rr = 0; rr < 2; rr++) {
        const int i = r + rr;
        if (i > NN) break;
#pragma unroll
        for (int q = 0; q < 2; q++) {
            const int j = j0 + q;
            if (j > NN) break;

            const bool iin = (i >= 2) && (i <= NN - 2);
            const bool jin = (j >= 2) && (j <= NN - 2);

            float s1 = 0.0f;
            if (iin && jin) {
                s1 += -u  * HYg(i-2, j-2) + u   * HYg(i-2, j)
                    + c01 * HYg(i-1, j-2) + c11 * HYg(i-1, j-1) + c21 * HYg(i-1, j)
                    + u   * HYg(i  , j-2) - u   * HYg(i  , j)
                    - u   * HYg(i+1, j-2) + u   * HYg(i+1, j);
            }
            if (i >= 1 && j <= NN - 5)
                s1 += KF0*HYg(i-1, j) + KF1*HYg(i-1, j+1) + KF2*HYg(i-1, j+2) + KF3*HYg(i-1, j+3);
            if (i <= NN - 1 && j >= 5)
                s1 += KB0*HYg(i, j-5) + KB1*HYg(i, j-4) + KB2*HYg(i, j-3) + KB3*HYg(i, j-2);
            if (iin && (j == 1 || j == 2))
                s1 += -HYg(i-1, j-1) + 3.0f*HYg(i-1, j) - 3.0f*HYg(i-1, j+1) + HYg(i-1, j+2);
            if (iin && (j == NN-2 || j == NN-1))
                s1 += HYg(i, j-4) - 3.0f*HYg(i, j-3) + 3.0f*HYg(i, j-2) - HYg(i, j-1);

            float s2 = 0.0f;
            if (iin && jin) {
                s2 += -u  * HXg(i-2, j-2) + c01 * HXg(i-2, j-1) + u * HXg(i-2, j) - u * HXg(i-2, j+1)
                    + c11 * HXg(i-1, j-1)
                    + u   * HXg(i  , j-2) + c21 * HXg(i  , j-1) - u * HXg(i  , j) + u * HXg(i  , j+1);
            }
            if (i <= NN - 5 && j >= 1)
                s2 += KF0*HXg(i, j-1) + KF1*HXg(i+1, j-1) + KF2*HXg(i+2, j-1) + KF3*HXg(i+3, j-1);
            if (i >= 5 && j <= NN - 1)
                s2 += KB0*HXg(i-5, j) + KB1*HXg(i-4, j) + KB2*HXg(i-3, j) + KB3*HXg(i-2, j);
            if ((i == 1 || i == 2) && jin)
                s2 += -HXg(i-1, j-1) + 3.0f*HXg(i, j-1) - 3.0f*HXg(i+1, j-1) + HXg(i+2, j-1);
            if ((i == NN-2 || i == NN-1) && jin)
                s2 += HXg(i-4, j) - 3.0f*HXg(i-3, j) + 3.0f*HXg(i-2, j) - HXg(i-1, j);

            const float val = ein[(size_t)i * EI + j] + CFLc * (s1 - s2);
            eo[(size_t)i * ES + j] = val;
            epo[(size_t)i * PE + j] = val;
        }
    }
#undef HXg
#undef HYg
}

// ---------------------------------------------------------------------------
// Faraday: Hx_out = Hx - CFL*s3 ; Hy_out = Hy + CFL*s4
// Block (64,4): thread = col pair j0, rows i = R0+2ty (even), i+1.
// RAWHY=true: Hy input is the raw odd-stride tensor (step 1).
// E input is ALWAYS padded (written by the amper in the same step).
// ---------------------------------------------------------------------------
template<bool RAWHY>
__global__ __launch_bounds__(256, 5) void faraday_kernel(
    const float* __restrict__ epad_in, const float* __restrict__ Hx,
    const float* __restrict__ hyp_in,
    float* __restrict__ hxo_d, float* __restrict__ hyo_d,
    float* __restrict__ hyp_out)
{
    constexpr int HYI = RAWHY ? HYS : PHY;
    constexpr size_t HYIB = RAWHY ? (size_t)HYSZ : (size_t)NN * PHY;
    constexpr bool V = !RAWHY;

    const int jb = blockIdx.x * 128;
    const int R0 = blockIdx.y * 8;
    const int tx = threadIdx.x;
    const int i0 = R0 + threadIdx.y * 2;
    const int j0 = jb + 2 * tx;
    const int b  = blockIdx.z;

    const float* __restrict__ ein = epad_in + (size_t)b * ES * PE;
    const float* __restrict__ hx  = Hx      + (size_t)b * HXSZ;
    const float* __restrict__ hyp = hyp_in  + (size_t)b * HYIB;
    float* __restrict__ hxo = hxo_d   + (size_t)b * HXSZ;
    float* __restrict__ hyo = hyo_d   + (size_t)b * HYSZ;
    float* __restrict__ hpo = hyp_out + (size_t)b * NN * PHY;

    const float u  = g_coef[0];
    const float dl = g_coef[1];
    const float c01 = u + dl - 0.5f;
    const float c11 = -2.0f * dl;
    const float c21 = dl + 0.5f - u;

    const bool fast = (R0 >= 8) && (R0 + 7 <= NN - 4) &&
                      (jb >= 128) && (jb + 127 <= NN - 4);

    if (fast) {
        float fm1[4], f0[8], f1[8], f2[6], f3[6], f4[2];
        ldrow<2, true>(fm1, ein + (i0-1) * PE + j0);
        ldrow<4, true>(f0 , ein + (i0  ) * PE + (j0-2));
        ldrow<4, true>(f1 , ein + (i0+1) * PE + (j0-2));
        ldrow<3, true>(f2 , ein + (i0+2) * PE + (j0-2));
        ldrow<3, true>(f3 , ein + (i0+3) * PE + (j0-2));
        ldrow<1, true>(f4 , ein + (i0+4) * PE + j0);

        float s3v[2][2], s4v[2][2];
#pragma unroll
        for (int q = 0; q < 2; q++) {
            s3v[0][q] = 0.5f * fm1[q+1]
                      - u * f0[q+1] + c01 * f0[q+2] + (u - 2.0f) * f0[q+3] - u * f0[q+4]
                      + (c11 - 1.5f) * f1[q+2] + 1.5f * f1[q+3]
                      + u * f2[q+1] + (c21 + 2.0f) * f2[q+2] - u * f2[q+3] + u * f2[q+4]
                      - 0.5f * f3[q+2];
            s4v[0][q] = -u * fm1[q] + u * fm1[q+2]
                      + c01 * f0[q+2] + (c11 - 1.5f) * f0[q+3]
                      + (c21 + 2.0f) * f0[q+4] - 0.5f * f0[q+5]
                      + 0.5f * f1[q+1] + (u - 2.0f) * f1[q+2] + 1.5f * f1[q+3] - u * f1[q+4]
                      - u * f2[q+2] + u * f2[q+4];
            s3v[1][q] = 0.5f * f0[q+3]
                      - u * f1[q+1] + c01 * f1[q+2] + (u - 2.0f) * f1[q+3] - u * f1[q+4]
                      + (c11 - 1.5f) * f2[q+2] + 1.5f * f2[q+3]
                      + u * f3[q+1] + (c21 + 2.0f) * f3[q+2] - u * f3[q+3] + u * f3[q+4]
                      - 0.5f * f4[q];
            s4v[1][q] = -u * f0[q+2] + u * f0[q+4]
                      + c01 * f1[q+2] + (c11 - 1.5f) * f1[q+3]
                      + (c21 + 2.0f) * f1[q+4] - 0.5f * f1[q+5]
                      + 0.5f * f2[q+1] + (u - 2.0f) * f2[q+2] + 1.5f * f2[q+3] - u * f2[q+4]
                      - u * f3[q+2] + u * f3[q+4];
        }

        // row i0 (even): hyo d_out f2 store is aligned (HYSZ, i0*HYS, j0 all even)
        {
            float hyv[2];
            ldrow<1, V>(hyv, hyp + (size_t)i0 * HYI + j0);
            float2 hxp = *reinterpret_cast<const float2*>(hx + (size_t)i0 * HXS + j0);
            const float x0 = hxp.x - CFLc * s3v[0][0];
            const float x1 = hxp.y - CFLc * s3v[0][1];
            const float y0 = hyv[0] + CFLc * s4v[0][0];
            const float y1 = hyv[1] + CFLc * s4v[0][1];
            *reinterpret_cast<float2*>(hxo + (size_t)i0 * HXS + j0) = make_float2(x0, x1);
            *reinterpret_cast<float2*>(hyo + (size_t)i0 * HYS + j0) = make_float2(y0, y1);
            *reinterpret_cast<float2*>(hpo + (size_t)i0 * PHY + j0) = make_float2(y0, y1);
        }
        {
            const int i = i0 + 1;
            float hyv[2];
            ldrow<1, V>(hyv, hyp + (size_t)i * HYI + j0);
            float2 hxp = *reinterpret_cast<const float2*>(hx + (size_t)i * HXS + j0);
            const float x0 = hxp.x - CFLc * s3v[1][0];
            const float x1 = hxp.y - CFLc * s3v[1][1];
            const float y0 = hyv[0] + CFLc * s4v[1][0];
            const float y1 = hyv[1] + CFLc * s4v[1][1];
            *reinterpret_cast<float2*>(hxo + (size_t)i * HXS + j0) = make_float2(x0, x1);
            hyo[(size_t)i * HYS + j0]     = y0;
            hyo[(size_t)i * HYS + j0 + 1] = y1;
            *reinterpret_cast<float2*>(hpo + (size_t)i * PHY + j0) = make_float2(y0, y1);
        }
        return;
    }

    // ---- generic path (edges) ----
#define EEg(rr,cc) ein[(rr) * PE + (cc)]
    for (int rr = 0; rr < 2; rr++) {
        const int i = i0 + rr;
        if (i >= NN) break;
#pragma unroll
        for (int q = 0; q < 2; q++) {
            const int j = j0 + q;
            if (j >= NN) break;

            if (i <= NN - 2) {
                float s3 = 0.0f;
                if (j >= 1 && j <= NN - 2) {
                    s3 += -u  * EEg(i  , j-1) + c01 * EEg(i  , j) + u * EEg(i  , j+1) - u * EEg(i  , j+2)
                        + c11 * EEg(i+1, j)
                        + u   * EEg(i+2, j-1) + c21 * EEg(i+2, j) - u * EEg(i+2, j+1) + u * EEg(i+2, j+2);
                }
                if (i <= NN - 4)
                    s3 += -1.5f * EEg(i+1, j) + 2.0f * EEg(i+2, j) - 0.5f * EEg(i+3, j);
                if (i >= 2)
                    s3 +=  0.5f * EEg(i-1, j+1) - 2.0f * EEg(i, j+1) + 1.5f * EEg(i+1, j+1);
                hxo[(size_t)i * HXS + j] = hx[(size_t)i * HXS + j] - CFLc * s3;
            }

            if (j <= NN - 2) {
                float s4 = 0.0f;
                if (i >= 1 && i <= NN - 2) {
                    s4 += -u  * EEg(i-1, j) + u * EEg(i-1, j+2)
                        + c01 * EEg(i  , j) + c11 * EEg(i, j+1) + c21 * EEg(i, j+2)
                        + u   * EEg(i+1, j) - u * EEg(i+1, j+2)
                        - u   * EEg(i+2, j) + u * EEg(i+2, j+2);
                }
                if (j <= NN - 4)
                    s4 += -1.5f * EEg(i, j+1) + 2.0f * EEg(i, j+2) - 0.5f * EEg(i, j+3);
                if (j >= 2)
                    s4 +=  0.5f * EEg(i+1, j-1) - 2.0f * EEg(i+1, j) + 1.5f * EEg(i+1, j+1);
                const float val = hyp[(size_t)i * HYI + j] + CFLc * s4;
                hyo[(size_t)i * HYS + j] = val;
                hpo[(size_t)i * PHY + j] = val;
            }
        }
    }
#undef EEg
}

// ---------------------------------------------------------------------------
extern "C" void kernel_launch(void* const* d_in, const int* in_sizes, int n_in,
                              void* d_out, int out_size)
{
    const float* E0    = (const float*)d_in[0];
    const float* Hx0   = (const float*)d_in[1];
    const float* Hy0   = (const float*)d_in[2];
    const float* beta  = (const float*)d_in[3];
    const float* delta = (const float*)d_in[4];
    const float* gamma = (const float*)d_in[5];

    float* out = (float*)d_out;
    const size_t esz  = (size_t)BB * ESZ;
    const size_t hxsz = (size_t)BB * HXSZ;
    const size_t hysz = (size_t)BB * HYSZ;

    float* E2  = out;
    float* Hx2 = E2  + esz;
    float* Hy2 = Hx2 + hxsz;
    float* E3  = Hy2 + hysz;
    float* Hx3 = E3  + esz;
    float* Hy3 = Hx3 + hxsz;
    float* E4  = Hy3 + hysz;
    float* Hx4 = E4  + esz;
    float* Hy4 = Hx4 + hxsz;

    float *EA, *EB, *HA, *HB;
    cudaGetSymbolAddress((void**)&EA, g_EpadA);
    cudaGetSymbolAddress((void**)&EB, g_EpadB);
    cudaGetSymbolAddress((void**)&HA, g_HyA);
    cudaGetSymbolAddress((void**)&HB, g_HyB);

    coef_kernel<<<1, 1>>>(beta, delta, gamma);

    dim3 blk(64, 4, 1);
    dim3 gE(17, (ES + 7) / 8, BB);   // 17 x 257 x 2
    dim3 gF(16, NN / 8, BB);         // 16 x 256 x 2

    // step 1 — raw inputs, no repack
    amper_kernel<true>   <<<gE, blk>>>(E0, Hx0, Hy0, E2, EB);
    faraday_kernel<true> <<<gF, blk>>>(EB, Hx0, Hy0, Hx2, Hy2, HB);
    // step 2 — padded inputs
    amper_kernel<false>  <<<gE, blk>>>(EB, Hx2, HB, E3, EA);
    faraday_kernel<false><<<gF, blk>>>(EA, Hx2, HB, Hx3, Hy3, HA);
    // step 3
    amper_kernel<false>  <<<gE, blk>>>(EA, Hx3, HA, E4, EB);
    faraday_kernel<false><<<gF, blk>>>(EB, Hx3, HA, Hx4, Hy4, HB);
}